// round 4
// baseline (speedup 1.0000x reference)
#include <cuda_runtime.h>
#include <math.h>

#define NB    128        // batch (graphs)
#define DD    64         // feature dim
#define N0V   1024       // nodes per graph, layer 0
#define NTOT  (NB*N0V)   // 131072
#define EPG   16384      // edges per graph (contiguous blocks)
#define ETOT  (NB*EPG)   // 2097152
#define KK1   820
#define KK2   656
#define KK3   525

#define INF_F __int_as_float(0x7f800000)

// ---------------- scratch (device globals; no allocations) ----------------
__device__ float g_xb[3][NTOT*DD];     // ping-pong x buffers
__device__ float g_msg[NTOT*DD];
__device__ float g_aggr[NTOT*DD];
__device__ int   g_src[ETOT];
__device__ int   g_dst[ETOT];
__device__ int   g_csr[ETOT];
__device__ int   g_rowstart[NTOT];
__device__ int   g_rowcnt[NTOT];
__device__ int   g_inv[NTOT];
__device__ float g_h[NB*2*DD];

// ---------------- init ----------------
__global__ void k_init_x(const int* __restrict__ ids, const float* __restrict__ emb,
                         float* __restrict__ x)
{
    int i = blockIdx.x * blockDim.x + threadIdx.x;
    if (i < NTOT*DD) x[i] = emb[ids[i >> 6] * DD + (i & 63)];
}

__global__ void k_copy_edges(const int* __restrict__ ei, int* __restrict__ src,
                             int* __restrict__ dst)
{
    int e = blockIdx.x * blockDim.x + threadIdx.x;
    if (e < ETOT) { src[e] = ei[e]; dst[e] = ei[ETOT + e]; }
}

__global__ void k_zero_h(float* __restrict__ h)
{
    int i = blockIdx.x * blockDim.x + threadIdx.x;
    if (i < NB*2*DD) h[i] = 0.f;
}

// ---------------- GEMM 1: msg = relu(x @ W^T + b), K = 64 ----------------
// block = 128 threads, 32 rows/block; thread computes 16 outputs of one row.
__global__ void k_gemm_relu(const float* __restrict__ A, const float* __restrict__ W,
                            const float* __restrict__ bias, float* __restrict__ out,
                            int nrows)
{
    __shared__ float sW[64][64];    // sW[k][o] = W[o][k] (transposed)
    __shared__ float sAt[64][32];   // sAt[k][r]
    __shared__ float sb[64];
    int tid = threadIdx.x;
    for (int idx = tid; idx < 64*64; idx += 128) {
        int o = idx >> 6, k = idx & 63;
        sW[k][o] = W[idx];
    }
    if (tid < 64) sb[tid] = bias[tid];
    int row0 = blockIdx.x * 32;
    for (int idx = tid; idx < 32*64; idx += 128) {
        int r = idx >> 6, k = idx & 63;
        int gr = row0 + r;
        sAt[k][r] = (gr < nrows) ? A[(size_t)gr*64 + k] : 0.f;
    }
    __syncthreads();
    int r = tid >> 2;
    int o0 = (tid & 3) << 4;
    float acc[16];
    #pragma unroll
    for (int j = 0; j < 16; j++) acc[j] = sb[o0 + j];
    #pragma unroll 8
    for (int k = 0; k < 64; k++) {
        float av = sAt[k][r];
        #pragma unroll
        for (int j = 0; j < 16; j++) acc[j] = fmaf(av, sW[k][o0 + j], acc[j]);
    }
    int gr = row0 + r;
    if (gr < nrows) {
        float* o = out + (size_t)gr*64 + o0;
        #pragma unroll
        for (int j = 0; j < 16; j++) o[j] = fmaxf(acc[j], 0.f);
    }
}

// ---------------- GEMM 2: out = relu([aggr, x] @ U^T), K = 128 ----------------
__global__ void k_gemm2_relu(const float* __restrict__ Agg, const float* __restrict__ X,
                             const float* __restrict__ U, float* __restrict__ out,
                             int nrows)
{
    __shared__ float sU[128][64];   // sU[k][o] = U[o][k]; k<64 -> aggr, k>=64 -> x
    __shared__ float sAt[64][32];
    __shared__ float sXt[64][32];
    int tid = threadIdx.x;
    for (int idx = tid; idx < 64*128; idx += 128) {
        int o = idx >> 7, k = idx & 127;
        sU[k][o] = U[idx];
    }
    int row0 = blockIdx.x * 32;
    for (int idx = tid; idx < 32*64; idx += 128) {
        int r = idx >> 6, k = idx & 63;
        int gr = row0 + r;
        sAt[k][r] = (gr < nrows) ? Agg[(size_t)gr*64 + k] : 0.f;
        sXt[k][r] = (gr < nrows) ? X[(size_t)gr*64 + k]   : 0.f;
    }
    __syncthreads();
    int r = tid >> 2;
    int o0 = (tid & 3) << 4;
    float acc[16];
    #pragma unroll
    for (int j = 0; j < 16; j++) acc[j] = 0.f;
    #pragma unroll 8
    for (int k = 0; k < 64; k++) {
        float av = sAt[k][r];
        #pragma unroll
        for (int j = 0; j < 16; j++) acc[j] = fmaf(av, sU[k][o0 + j], acc[j]);
    }
    #pragma unroll 8
    for (int k = 0; k < 64; k++) {
        float xv = sXt[k][r];
        #pragma unroll
        for (int j = 0; j < 16; j++) acc[j] = fmaf(xv, sU[64 + k][o0 + j], acc[j]);
    }
    int gr = row0 + r;
    if (gr < nrows) {
        float* o = out + (size_t)gr*64 + o0;
        #pragma unroll
        for (int j = 0; j < 16; j++) o[j] = fmaxf(acc[j], 0.f);
    }
}

// ---------------- per-graph CSR build (block per graph) ----------------
__global__ void k_csr(const int* __restrict__ src, const int* __restrict__ dst, int n,
                      int* __restrict__ rowstart, int* __restrict__ rowcnt,
                      int* __restrict__ csr)
{
    __shared__ int cnt[1024];
    __shared__ int offs[1024];
    __shared__ int part[256];
    int g = blockIdx.x, tid = threadIdx.x;     // 256 threads
    for (int i = tid; i < n; i += 256) cnt[i] = 0;
    __syncthreads();
    int e0 = g * EPG;
    int nb = g * n;
    for (int e = tid; e < EPG; e += 256) {
        int s = src[e0 + e];
        if (s >= 0) atomicAdd(&cnt[dst[e0 + e] - nb], 1);
    }
    __syncthreads();
    int chunk = (n + 255) >> 8;
    int base = tid * chunk;
    int run = 0;
    for (int j = 0; j < chunk; j++) {
        int i = base + j;
        if (i < n) { offs[i] = run; run += cnt[i]; }
    }
    part[tid] = run;
    __syncthreads();
    if (tid == 0) {
        int acc = 0;
        for (int t = 0; t < 256; t++) { int v = part[t]; part[t] = acc; acc += v; }
    }
    __syncthreads();
    int add = part[tid];
    for (int j = 0; j < chunk; j++) {
        int i = base + j;
        if (i < n) offs[i] += add;
    }
    __syncthreads();
    for (int i = tid; i < n; i += 256) {
        rowstart[nb + i] = offs[i];
        rowcnt[nb + i]   = cnt[i];
    }
    __syncthreads();
    for (int e = tid; e < EPG; e += 256) {
        int s = src[e0 + e];
        if (s >= 0) {
            int pos = atomicAdd(&offs[dst[e0 + e] - nb], 1);
            csr[e0 + pos] = s;   // global src id
        }
    }
}

// ---------------- gather-max aggregation (warp per dst node) ----------------
// Unrolled by 4: four independent 256B row loads in flight per warp
// (cyc/LDG ~ lat/MLP -> expect ~2-3x vs serial gather).
__global__ void k_aggr(const float* __restrict__ msg, const int* __restrict__ rowstart,
                       const int* __restrict__ rowcnt, const int* __restrict__ csr,
                       float* __restrict__ aggr, int n, int n_nodes)
{
    int warp = (blockIdx.x * blockDim.x + threadIdx.x) >> 5;
    int lane = threadIdx.x & 31;
    if (warp >= n_nodes) return;
    const float2* m2 = (const float2*)msg;
    float2 acc = m2[(size_t)warp*32 + lane];            // self-loop init
    int g = warp / n;
    int st = rowstart[warp], c = rowcnt[warp];
    const int* lst = csr + (size_t)g * EPG + st;
    int t = 0;
    for (; t + 4 <= c; t += 4) {
        int s0 = lst[t], s1 = lst[t+1], s2 = lst[t+2], s3 = lst[t+3];
        float2 v0 = m2[(size_t)s0*32 + lane];
        float2 v1 = m2[(size_t)s1*32 + lane];
        float2 v2 = m2[(size_t)s2*32 + lane];
        float2 v3 = m2[(size_t)s3*32 + lane];
        v0.x = fmaxf(v0.x, v1.x); v0.y = fmaxf(v0.y, v1.y);
        v2.x = fmaxf(v2.x, v3.x); v2.y = fmaxf(v2.y, v3.y);
        v0.x = fmaxf(v0.x, v2.x); v0.y = fmaxf(v0.y, v2.y);
        acc.x = fmaxf(acc.x, v0.x); acc.y = fmaxf(acc.y, v0.y);
    }
    for (; t < c; t++) {
        int s = lst[t];
        float2 v = m2[(size_t)s*32 + lane];
        acc.x = fmaxf(acc.x, v.x);
        acc.y = fmaxf(acc.y, v.y);
    }
    ((float2*)aggr)[(size_t)warp*32 + lane] = acc;
}

// ---------------- TopK pooling (block per graph, 1024 threads) ----------------
// jax.lax.top_k tie-break: equal scores -> lower index first. Comparator must match
// (scores are massively degenerate here: only 4 distinct input embeddings).
__global__ void k_topk(const float* __restrict__ x, const float* __restrict__ p,
                       int n, int K, float* __restrict__ xnew, int* __restrict__ inv)
{
    __shared__ float sval[1024];
    __shared__ int   sidx[1024];
    __shared__ float stan[1024];
    __shared__ float pp[64];
    __shared__ float sinv;
    int g = blockIdx.x, tid = threadIdx.x;
    if (tid < 64) pp[tid] = p[tid];
    __syncthreads();
    if (tid == 0) {
        float s = 0.f;
        for (int k = 0; k < 64; k++) s += pp[k]*pp[k];
        sinv = 1.f / sqrtf(s);
    }
    int warp = tid >> 5, lane = tid & 31;
    const float2* pv2 = (const float2*)pp;
    for (int i = warp; i < 1024; i += 32) {
        float dsum = 0.f;
        if (i < n) {
            const float2* row = (const float2*)(x + ((size_t)g*n + i)*64);
            float2 a = row[lane];
            float2 b = pv2[lane];
            dsum = a.x*b.x + a.y*b.y;
            #pragma unroll
            for (int o = 16; o > 0; o >>= 1) dsum += __shfl_down_sync(0xffffffffu, dsum, o);
        }
        if (lane == 0) {
            sval[i] = (i < n) ? dsum : -INF_F;
            sidx[i] = i;
        }
    }
    __syncthreads();
    // bitonic sort: descending by value, ascending index on ties
    for (int ksz = 2; ksz <= 1024; ksz <<= 1) {
        for (int j = ksz >> 1; j > 0; j >>= 1) {
            int ixj = tid ^ j;
            if (ixj > tid) {
                float va = sval[tid], vb = sval[ixj];
                int   ia = sidx[tid], ib = sidx[ixj];
                bool a_first = (va > vb) || (va == vb && ia < ib);
                bool descHere = ((tid & ksz) == 0);
                if (descHere != a_first) {
                    sval[tid] = vb; sval[ixj] = va;
                    sidx[tid] = ib; sidx[ixj] = ia;
                }
            }
            __syncthreads();
        }
    }
    for (int i = tid; i < n; i += 1024) inv[g*n + i] = -1;
    __syncthreads();
    if (tid < K) {
        inv[g*n + sidx[tid]] = g*K + tid;
        stan[tid] = tanhf(sval[tid] * sinv);
    }
    __syncthreads();
    for (int idx = tid; idx < K*64; idx += 1024) {
        int j = idx >> 6, k = idx & 63;
        xnew[((size_t)g*K + j)*64 + k] = x[((size_t)g*n + sidx[j])*64 + k] * stan[j];
    }
}

// ---------------- edge relabel ----------------
__global__ void k_remap(int* __restrict__ src, int* __restrict__ dst,
                        const int* __restrict__ inv)
{
    int e = blockIdx.x * blockDim.x + threadIdx.x;
    if (e >= ETOT) return;
    int s = src[e];
    if (s < 0) return;
    int ns = inv[s], nd = inv[dst[e]];
    if (ns < 0 || nd < 0) { src[e] = -1; dst[e] = -1; }
    else                  { src[e] = ns; dst[e] = nd; }
}

// ---------------- readout: h[g] += [max_k, mean_k] ----------------
// 256 threads: 4 row-strided partials per dim, smem combine (4x parallelism vs 64-thread scan).
__global__ void k_readout(const float* __restrict__ x, int K, float* __restrict__ h)
{
    __shared__ float smx[4][64];
    __shared__ float ssm[4][64];
    int g = blockIdx.x;
    int d = threadIdx.x & 63;
    int part = threadIdx.x >> 6;       // 0..3
    float mx = -INF_F, sm = 0.f;
    const float* base = x + (size_t)g*K*64 + d;
    int j = part;
    for (; j + 16 <= K; j += 16) {     // 4 loads/iter in flight per thread
        float v0 = base[(size_t)(j     )*64];
        float v1 = base[(size_t)(j +  4)*64];
        float v2 = base[(size_t)(j +  8)*64];
        float v3 = base[(size_t)(j + 12)*64];
        mx = fmaxf(mx, fmaxf(fmaxf(v0, v1), fmaxf(v2, v3)));
        sm += (v0 + v1) + (v2 + v3);
    }
    for (; j < K; j += 4) {
        float v = base[(size_t)j*64];
        mx = fmaxf(mx, v);
        sm += v;
    }
    smx[part][d] = mx;
    ssm[part][d] = sm;
    __syncthreads();
    if (part == 0) {
        mx = fmaxf(fmaxf(smx[0][d], smx[1][d]), fmaxf(smx[2][d], smx[3][d]));
        sm = (ssm[0][d] + ssm[1][d]) + (ssm[2][d] + ssm[3][d]);
        h[g*128 + d]      += mx;
        h[g*128 + 64 + d] += sm / (float)K;
    }
}

// ---------------- final MLP (block per graph) ----------------
__global__ void k_mlp(const float* __restrict__ h,
                      const float* __restrict__ l1W, const float* __restrict__ l1b,
                      const float* __restrict__ l2W, const float* __restrict__ l2b,
                      const float* __restrict__ l3W, const float* __restrict__ l3b,
                      float* __restrict__ out)
{
    int g = blockIdx.x, o = threadIdx.x;   // 64 threads
    __shared__ float sh[128], t1[64], t2[64];
    sh[o]      = h[g*128 + o];
    sh[64 + o] = h[g*128 + 64 + o];
    __syncthreads();
    float a = l1b[o];
    for (int k = 0; k < 128; k++) a = fmaf(sh[k], l1W[o*128 + k], a);
    t1[o] = fmaxf(a, 0.f);
    __syncthreads();
    float b = l2b[o];
    for (int k = 0; k < 64; k++) b = fmaf(t1[k], l2W[o*64 + k], b);
    t2[o] = fmaxf(b, 0.f);
    __syncthreads();
    float c = l3b[o];
    for (int k = 0; k < 64; k++) c = fmaf(t2[k], l3W[o*64 + k], c);
    out[g*64 + o] = 1.f / (1.f + expf(-c));
}

// ---------------- batch output (constant): repeat(arange(B), K3) ----------------
__global__ void k_batch(float* __restrict__ out, int total)
{
    int i = blockIdx.x * blockDim.x + threadIdx.x;
    if (i < total) out[NB*DD + i] = (float)(i / KK3);
}

// ---------------- host ----------------
extern "C" void kernel_launch(void* const* d_in, const int* in_sizes, int n_in,
                              void* d_out, int out_size)
{
    const int*   x_ids = (const int*)d_in[0];
    const int*   ei    = (const int*)d_in[1];
    const float* emb   = (const float*)d_in[2];
    const float* W[3]  = {(const float*)d_in[3], (const float*)d_in[7],  (const float*)d_in[11]};
    const float* bb[3] = {(const float*)d_in[4], (const float*)d_in[8],  (const float*)d_in[12]};
    const float* U[3]  = {(const float*)d_in[5], (const float*)d_in[9],  (const float*)d_in[13]};
    const float* p[3]  = {(const float*)d_in[6], (const float*)d_in[10], (const float*)d_in[14]};
    const float* l1W = (const float*)d_in[15];
    const float* l1b = (const float*)d_in[16];
    const float* l2W = (const float*)d_in[17];
    const float* l2b = (const float*)d_in[18];
    const float* l3W = (const float*)d_in[19];
    const float* l3b = (const float*)d_in[20];

    float *xbase, *msg, *aggr, *h;
    int *src, *dst, *csr, *rowstart, *rowcnt, *inv;
    cudaGetSymbolAddress((void**)&xbase,    g_xb);
    cudaGetSymbolAddress((void**)&msg,      g_msg);
    cudaGetSymbolAddress((void**)&aggr,     g_aggr);
    cudaGetSymbolAddress((void**)&src,      g_src);
    cudaGetSymbolAddress((void**)&dst,      g_dst);
    cudaGetSymbolAddress((void**)&csr,      g_csr);
    cudaGetSymbolAddress((void**)&rowstart, g_rowstart);
    cudaGetSymbolAddress((void**)&rowcnt,   g_rowcnt);
    cudaGetSymbolAddress((void**)&inv,      g_inv);
    cudaGetSymbolAddress((void**)&h,        g_h);

    float* xs[3] = {xbase, xbase + (size_t)NTOT*DD, xbase + (size_t)2*NTOT*DD};

    k_init_x<<<(NTOT*DD + 255)/256, 256>>>(x_ids, emb, xs[0]);
    k_copy_edges<<<(ETOT + 255)/256, 256>>>(ei, src, dst);
    k_zero_h<<<(NB*2*DD + 255)/256, 256>>>(h);

    int ns[4] = {N0V, KK1, KK2, KK3};
    int cur = 0;
    for (int l = 0; l < 3; l++) {
        int n = ns[l], K = ns[l + 1];
        int nrows = NB * n;
        float* xc = xs[cur];
        float* xo = xs[(cur + 1) % 3];
        float* xn = xs[(cur + 2) % 3];

        k_gemm_relu<<<(nrows + 31)/32, 128>>>(xc, W[l], bb[l], msg, nrows);
        k_csr<<<NB, 256>>>(src, dst, n, rowstart, rowcnt, csr);
        k_aggr<<<(nrows + 7)/8, 256>>>(msg, rowstart, rowcnt, csr, aggr, n, nrows);
        k_gemm2_relu<<<(nrows + 31)/32, 128>>>(aggr, xc, U[l], xo, nrows);
        k_topk<<<NB, 1024>>>(xo, p[l], n, K, xn, inv);
        if (l < 2) k_remap<<<(ETOT + 255)/256, 256>>>(src, dst, inv);
        k_readout<<<NB, 256>>>(xn, K, h);
        cur = (cur + 2) % 3;
    }

    k_mlp<<<NB, 64>>>(h, l1W, l1b, l2W, l2b, l3W, l3b, (float*)d_out);

    if (out_size > NB*DD) {
        int total = out_size - NB*DD;
        k_batch<<<(total + 255)/256, 256>>>((float*)d_out, total);
    }
}

// round 5
// speedup vs baseline: 2.4944x; 2.4944x over previous
#include <cuda_runtime.h>
#include <math.h>

#define NB    128        // batch (graphs)
#define DD    64         // feature dim
#define N0V   1024       // nodes per graph, layer 0
#define NTOT  (NB*N0V)   // 131072
#define EPG   16384      // edges per graph (contiguous blocks)
#define ETOT  (NB*EPG)   // 2097152
#define KK1   820
#define KK2   656
#define KK3   525

#define INF_F __int_as_float(0x7f800000)

// ---------------- scratch (device globals; no allocations) ----------------
__device__ float g_xb[3][NTOT*DD];     // ping-pong x buffers
__device__ float g_msg[NTOT*DD];
__device__ float g_aggr[NTOT*DD];
__device__ int   g_src[ETOT];
__device__ int   g_dst[ETOT];
__device__ int   g_csr[ETOT];
__device__ int   g_rowstart[NTOT];
__device__ int   g_rowcnt[NTOT];
__device__ int   g_inv[NTOT];
__device__ float g_h[NB*2*DD];

// ---------------- init ----------------
__global__ void k_init_x(const int* __restrict__ ids, const float* __restrict__ emb,
                         float* __restrict__ x)
{
    int i = blockIdx.x * blockDim.x + threadIdx.x;
    if (i < NTOT*DD) x[i] = emb[ids[i >> 6] * DD + (i & 63)];
}

__global__ void k_copy_edges(const int* __restrict__ ei, int* __restrict__ src,
                             int* __restrict__ dst)
{
    int e = blockIdx.x * blockDim.x + threadIdx.x;
    if (e < ETOT) { src[e] = ei[e]; dst[e] = ei[ETOT + e]; }
}

__global__ void k_zero_h(float* __restrict__ h)
{
    int i = blockIdx.x * blockDim.x + threadIdx.x;
    if (i < NB*2*DD) h[i] = 0.f;
}

// ---------------- GEMM 1: msg = relu(x @ W^T + b), K = 64 ----------------
// 128 threads, 128 rows x 64 cols per block; 8x8 register tile per thread.
// smem bytes/FMA-lane = 1.0 -> FFMA-issue-bound, not crossbar-bound.
__global__ void __launch_bounds__(128) k_gemm_relu(
        const float* __restrict__ A, const float* __restrict__ W,
        const float* __restrict__ bias, float* __restrict__ out, int nrows)
{
    __shared__ float sW[64][65];    // sW[k][o] = W[o][k]; pad 65: conflict-free T-write
    __shared__ float sAt[64][129];  // sAt[k][row]; pad 129: conflict-free T-write
    __shared__ float sb[64];
    int tid = threadIdx.x;
    for (int idx = tid; idx < 64*64; idx += 128) {
        int o = idx >> 6, k = idx & 63;
        sW[k][o] = W[idx];
    }
    if (tid < 64) sb[tid] = bias[tid];
    size_t row0 = (size_t)blockIdx.x * 128;
    const float* Ab = A + row0 * 64;
    for (int idx = tid; idx < 128*64; idx += 128) {
        int r = idx >> 6, k = idx & 63;
        sAt[k][r] = Ab[idx];
    }
    __syncthreads();

    int tr = tid >> 3;          // 0..15 : rows tr+16*i
    int tc = (tid & 7) << 3;    // 0..56 : cols tc..tc+7
    float acc[8][8];
    #pragma unroll
    for (int i = 0; i < 8; i++)
        #pragma unroll
        for (int j = 0; j < 8; j++) acc[i][j] = sb[tc + j];

    #pragma unroll 4
    for (int k = 0; k < 64; k++) {
        float a[8], w[8];
        #pragma unroll
        for (int i = 0; i < 8; i++) a[i] = sAt[k][tr + 16*i];
        #pragma unroll
        for (int j = 0; j < 8; j++) w[j] = sW[k][tc + j];
        #pragma unroll
        for (int i = 0; i < 8; i++)
            #pragma unroll
            for (int j = 0; j < 8; j++) acc[i][j] = fmaf(a[i], w[j], acc[i][j]);
    }

    #pragma unroll
    for (int i = 0; i < 8; i++) {
        float* o = out + (row0 + tr + 16*i) * 64 + tc;
        #pragma unroll
        for (int j = 0; j < 8; j++) o[j] = fmaxf(acc[i][j], 0.f);
    }
}

// ---------------- GEMM 2: out = relu([aggr, x] @ U^T), K = 128 ----------------
// Two K=64 phases sharing one A-tile buffer (aggr then x).
__global__ void __launch_bounds__(128) k_gemm2_relu(
        const float* __restrict__ Agg, const float* __restrict__ X,
        const float* __restrict__ U, float* __restrict__ out, int nrows)
{
    __shared__ float sU[128][65];   // sU[k][o] = U[o][k]; k<64 aggr-half, k>=64 x-half
    __shared__ float sAt[64][129];
    int tid = threadIdx.x;
    for (int idx = tid; idx < 64*128; idx += 128) {
        int o = idx >> 7, k = idx & 127;
        sU[k][o] = U[idx];
    }
    size_t row0 = (size_t)blockIdx.x * 128;
    int tr = tid >> 3;
    int tc = (tid & 7) << 3;
    float acc[8][8];
    #pragma unroll
    for (int i = 0; i < 8; i++)
        #pragma unroll
        for (int j = 0; j < 8; j++) acc[i][j] = 0.f;

    #pragma unroll
    for (int ph = 0; ph < 2; ph++) {
        const float* Ab = (ph == 0 ? Agg : X) + row0 * 64;
        if (ph) __syncthreads();            // all warps done reading phase-0 tile
        for (int idx = tid; idx < 128*64; idx += 128) {
            int r = idx >> 6, k = idx & 63;
            sAt[k][r] = Ab[idx];
        }
        __syncthreads();
        int kofs = ph << 6;
        #pragma unroll 4
        for (int k = 0; k < 64; k++) {
            float a[8], w[8];
            #pragma unroll
            for (int i = 0; i < 8; i++) a[i] = sAt[k][tr + 16*i];
            #pragma unroll
            for (int j = 0; j < 8; j++) w[j] = sU[kofs + k][tc + j];
            #pragma unroll
            for (int i = 0; i < 8; i++)
                #pragma unroll
                for (int j = 0; j < 8; j++) acc[i][j] = fmaf(a[i], w[j], acc[i][j]);
        }
    }

    #pragma unroll
    for (int i = 0; i < 8; i++) {
        float* o = out + (row0 + tr + 16*i) * 64 + tc;
        #pragma unroll
        for (int j = 0; j < 8; j++) o[j] = fmaxf(acc[i][j], 0.f);
    }
}

// ---------------- per-graph CSR build (block per graph) ----------------
__global__ void k_csr(const int* __restrict__ src, const int* __restrict__ dst, int n,
                      int* __restrict__ rowstart, int* __restrict__ rowcnt,
                      int* __restrict__ csr)
{
    __shared__ int cnt[1024];
    __shared__ int offs[1024];
    __shared__ int part[256];
    int g = blockIdx.x, tid = threadIdx.x;     // 256 threads
    for (int i = tid; i < n; i += 256) cnt[i] = 0;
    __syncthreads();
    int e0 = g * EPG;
    int nb = g * n;
    for (int e = tid; e < EPG; e += 256) {
        int s = src[e0 + e];
        if (s >= 0) atomicAdd(&cnt[dst[e0 + e] - nb], 1);
    }
    __syncthreads();
    int chunk = (n + 255) >> 8;
    int base = tid * chunk;
    int run = 0;
    for (int j = 0; j < chunk; j++) {
        int i = base + j;
        if (i < n) { offs[i] = run; run += cnt[i]; }
    }
    part[tid] = run;
    __syncthreads();
    if (tid == 0) {
        int acc = 0;
        for (int t = 0; t < 256; t++) { int v = part[t]; part[t] = acc; acc += v; }
    }
    __syncthreads();
    int add = part[tid];
    for (int j = 0; j < chunk; j++) {
        int i = base + j;
        if (i < n) offs[i] += add;
    }
    __syncthreads();
    for (int i = tid; i < n; i += 256) {
        rowstart[nb + i] = offs[i];
        rowcnt[nb + i]   = cnt[i];
    }
    __syncthreads();
    for (int e = tid; e < EPG; e += 256) {
        int s = src[e0 + e];
        if (s >= 0) {
            int pos = atomicAdd(&offs[dst[e0 + e] - nb], 1);
            csr[e0 + pos] = s;   // global src id
        }
    }
}

// ---------------- gather-max aggregation (warp per dst node) ----------------
// Unrolled by 4: four independent 256B row loads in flight per warp.
__global__ void k_aggr(const float* __restrict__ msg, const int* __restrict__ rowstart,
                       const int* __restrict__ rowcnt, const int* __restrict__ csr,
                       float* __restrict__ aggr, int n, int n_nodes)
{
    int warp = (blockIdx.x * blockDim.x + threadIdx.x) >> 5;
    int lane = threadIdx.x & 31;
    if (warp >= n_nodes) return;
    const float2* m2 = (const float2*)msg;
    float2 acc = m2[(size_t)warp*32 + lane];            // self-loop init
    int g = warp / n;
    int st = rowstart[warp], c = rowcnt[warp];
    const int* lst = csr + (size_t)g * EPG + st;
    int t = 0;
    for (; t + 4 <= c; t += 4) {
        int s0 = lst[t], s1 = lst[t+1], s2 = lst[t+2], s3 = lst[t+3];
        float2 v0 = m2[(size_t)s0*32 + lane];
        float2 v1 = m2[(size_t)s1*32 + lane];
        float2 v2 = m2[(size_t)s2*32 + lane];
        float2 v3 = m2[(size_t)s3*32 + lane];
        v0.x = fmaxf(v0.x, v1.x); v0.y = fmaxf(v0.y, v1.y);
        v2.x = fmaxf(v2.x, v3.x); v2.y = fmaxf(v2.y, v3.y);
        v0.x = fmaxf(v0.x, v2.x); v0.y = fmaxf(v0.y, v2.y);
        acc.x = fmaxf(acc.x, v0.x); acc.y = fmaxf(acc.y, v0.y);
    }
    for (; t < c; t++) {
        int s = lst[t];
        float2 v = m2[(size_t)s*32 + lane];
        acc.x = fmaxf(acc.x, v.x);
        acc.y = fmaxf(acc.y, v.y);
    }
    ((float2*)aggr)[(size_t)warp*32 + lane] = acc;
}

// ---------------- TopK pooling (block per graph, 1024 threads) ----------------
// jax.lax.top_k tie-break: equal scores -> lower index first. Comparator must match
// (scores are massively degenerate here: only 4 distinct input embeddings).
__global__ void k_topk(const float* __restrict__ x, const float* __restrict__ p,
                       int n, int K, float* __restrict__ xnew, int* __restrict__ inv)
{
    __shared__ float sval[1024];
    __shared__ int   sidx[1024];
    __shared__ float stan[1024];
    __shared__ float pp[64];
    __shared__ float sinv;
    int g = blockIdx.x, tid = threadIdx.x;
    if (tid < 64) pp[tid] = p[tid];
    __syncthreads();
    if (tid == 0) {
        float s = 0.f;
        for (int k = 0; k < 64; k++) s += pp[k]*pp[k];
        sinv = 1.f / sqrtf(s);
    }
    int warp = tid >> 5, lane = tid & 31;
    const float2* pv2 = (const float2*)pp;
    for (int i = warp; i < 1024; i += 32) {
        float dsum = 0.f;
        if (i < n) {
            const float2* row = (const float2*)(x + ((size_t)g*n + i)*64);
            float2 a = row[lane];
            float2 b = pv2[lane];
            dsum = a.x*b.x + a.y*b.y;
            #pragma unroll
            for (int o = 16; o > 0; o >>= 1) dsum += __shfl_down_sync(0xffffffffu, dsum, o);
        }
        if (lane == 0) {
            sval[i] = (i < n) ? dsum : -INF_F;
            sidx[i] = i;
        }
    }
    __syncthreads();
    // bitonic sort: descending by value, ascending index on ties
    for (int ksz = 2; ksz <= 1024; ksz <<= 1) {
        for (int j = ksz >> 1; j > 0; j >>= 1) {
            int ixj = tid ^ j;
            if (ixj > tid) {
                float va = sval[tid], vb = sval[ixj];
                int   ia = sidx[tid], ib = sidx[ixj];
                bool a_first = (va > vb) || (va == vb && ia < ib);
                bool descHere = ((tid & ksz) == 0);
                if (descHere != a_first) {
                    sval[tid] = vb; sval[ixj] = va;
                    sidx[tid] = ib; sidx[ixj] = ia;
                }
            }
            __syncthreads();
        }
    }
    for (int i = tid; i < n; i += 1024) inv[g*n + i] = -1;
    __syncthreads();
    if (tid < K) {
        inv[g*n + sidx[tid]] = g*K + tid;
        stan[tid] = tanhf(sval[tid] * sinv);
    }
    __syncthreads();
    for (int idx = tid; idx < K*64; idx += 1024) {
        int j = idx >> 6, k = idx & 63;
        xnew[((size_t)g*K + j)*64 + k] = x[((size_t)g*n + sidx[j])*64 + k] * stan[j];
    }
}

// ---------------- edge relabel ----------------
__global__ void k_remap(int* __restrict__ src, int* __restrict__ dst,
                        const int* __restrict__ inv)
{
    int e = blockIdx.x * blockDim.x + threadIdx.x;
    if (e >= ETOT) return;
    int s = src[e];
    if (s < 0) return;
    int ns = inv[s], nd = inv[dst[e]];
    if (ns < 0 || nd < 0) { src[e] = -1; dst[e] = -1; }
    else                  { src[e] = ns; dst[e] = nd; }
}

// ---------------- readout: h[g] += [max_k, mean_k] ----------------
__global__ void k_readout(const float* __restrict__ x, int K, float* __restrict__ h)
{
    __shared__ float smx[4][64];
    __shared__ float ssm[4][64];
    int g = blockIdx.x;
    int d = threadIdx.x & 63;
    int part = threadIdx.x >> 6;       // 0..3
    float mx = -INF_F, sm = 0.f;
    const float* base = x + (size_t)g*K*64 + d;
    int j = part;
    for (; j + 16 <= K; j += 16) {     // 4 loads/iter in flight per thread
        float v0 = base[(size_t)(j     )*64];
        float v1 = base[(size_t)(j +  4)*64];
        float v2 = base[(size_t)(j +  8)*64];
        float v3 = base[(size_t)(j + 12)*64];
        mx = fmaxf(mx, fmaxf(fmaxf(v0, v1), fmaxf(v2, v3)));
        sm += (v0 + v1) + (v2 + v3);
    }
    for (; j < K; j += 4) {
        float v = base[(size_t)j*64];
        mx = fmaxf(mx, v);
        sm += v;
    }
    smx[part][d] = mx;
    ssm[part][d] = sm;
    __syncthreads();
    if (part == 0) {
        mx = fmaxf(fmaxf(smx[0][d], smx[1][d]), fmaxf(smx[2][d], smx[3][d]));
        sm = (ssm[0][d] + ssm[1][d]) + (ssm[2][d] + ssm[3][d]);
        h[g*128 + d]      += mx;
        h[g*128 + 64 + d] += sm / (float)K;
    }
}

// ---------------- final MLP (block per graph) ----------------
__global__ void k_mlp(const float* __restrict__ h,
                      const float* __restrict__ l1W, const float* __restrict__ l1b,
                      const float* __restrict__ l2W, const float* __restrict__ l2b,
                      const float* __restrict__ l3W, const float* __restrict__ l3b,
                      float* __restrict__ out)
{
    int g = blockIdx.x, o = threadIdx.x;   // 64 threads
    __shared__ float sh[128], t1[64], t2[64];
    sh[o]      = h[g*128 + o];
    sh[64 + o] = h[g*128 + 64 + o];
    __syncthreads();
    float a = l1b[o];
    for (int k = 0; k < 128; k++) a = fmaf(sh[k], l1W[o*128 + k], a);
    t1[o] = fmaxf(a, 0.f);
    __syncthreads();
    float b = l2b[o];
    for (int k = 0; k < 64; k++) b = fmaf(t1[k], l2W[o*64 + k], b);
    t2[o] = fmaxf(b, 0.f);
    __syncthreads();
    float c = l3b[o];
    for (int k = 0; k < 64; k++) c = fmaf(t2[k], l3W[o*64 + k], c);
    out[g*64 + o] = 1.f / (1.f + expf(-c));
}

// ---------------- batch output (constant): repeat(arange(B), K3) ----------------
__global__ void k_batch(float* __restrict__ out, int total)
{
    int i = blockIdx.x * blockDim.x + threadIdx.x;
    if (i < total) out[NB*DD + i] = (float)(i / KK3);
}

// ---------------- host ----------------
extern "C" void kernel_launch(void* const* d_in, const int* in_sizes, int n_in,
                              void* d_out, int out_size)
{
    const int*   x_ids = (const int*)d_in[0];
    const int*   ei    = (const int*)d_in[1];
    const float* emb   = (const float*)d_in[2];
    const float* W[3]  = {(const float*)d_in[3], (const float*)d_in[7],  (const float*)d_in[11]};
    const float* bb[3] = {(const float*)d_in[4], (const float*)d_in[8],  (const float*)d_in[12]};
    const float* U[3]  = {(const float*)d_in[5], (const float*)d_in[9],  (const float*)d_in[13]};
    const float* p[3]  = {(const float*)d_in[6], (const float*)d_in[10], (const float*)d_in[14]};
    const float* l1W = (const float*)d_in[15];
    const float* l1b = (const float*)d_in[16];
    const float* l2W = (const float*)d_in[17];
    const float* l2b = (const float*)d_in[18];
    const float* l3W = (const float*)d_in[19];
    const float* l3b = (const float*)d_in[20];

    float *xbase, *msg, *aggr, *h;
    int *src, *dst, *csr, *rowstart, *rowcnt, *inv;
    cudaGetSymbolAddress((void**)&xbase,    g_xb);
    cudaGetSymbolAddress((void**)&msg,      g_msg);
    cudaGetSymbolAddress((void**)&aggr,     g_aggr);
    cudaGetSymbolAddress((void**)&src,      g_src);
    cudaGetSymbolAddress((void**)&dst,      g_dst);
    cudaGetSymbolAddress((void**)&csr,      g_csr);
    cudaGetSymbolAddress((void**)&rowstart, g_rowstart);
    cudaGetSymbolAddress((void**)&rowcnt,   g_rowcnt);
    cudaGetSymbolAddress((void**)&inv,      g_inv);
    cudaGetSymbolAddress((void**)&h,        g_h);

    float* xs[3] = {xbase, xbase + (size_t)NTOT*DD, xbase + (size_t)2*NTOT*DD};

    k_init_x<<<(NTOT*DD + 255)/256, 256>>>(x_ids, emb, xs[0]);
    k_copy_edges<<<(ETOT + 255)/256, 256>>>(ei, src, dst);
    k_zero_h<<<(NB*2*DD + 255)/256, 256>>>(h);

    int ns[4] = {N0V, KK1, KK2, KK3};
    int cur = 0;
    for (int l = 0; l < 3; l++) {
        int n = ns[l], K = ns[l + 1];
        int nrows = NB * n;
        float* xc = xs[cur];
        float* xo = xs[(cur + 1) % 3];
        float* xn = xs[(cur + 2) % 3];

        k_gemm_relu<<<nrows/128, 128>>>(xc, W[l], bb[l], msg, nrows);
        k_csr<<<NB, 256>>>(src, dst, n, rowstart, rowcnt, csr);
        k_aggr<<<(nrows + 7)/8, 256>>>(msg, rowstart, rowcnt, csr, aggr, n, nrows);
        k_gemm2_relu<<<nrows/128, 128>>>(aggr, xc, U[l], xo, nrows);
        k_topk<<<NB, 1024>>>(xo, p[l], n, K, xn, inv);
        if (l < 2) k_remap<<<(ETOT + 255)/256, 256>>>(src, dst, inv);
        k_readout<<<NB, 256>>>(xn, K, h);
        cur = (cur + 2) % 3;
    }

    k_mlp<<<NB, 64>>>(h, l1W, l1b, l2W, l2b, l3W, l3b, (float*)d_out);

    if (out_size > NB*DD) {
        int total = out_size - NB*DD;
        k_batch<<<(total + 255)/256, 256>>>((float*)d_out, total);
    }
}

// round 6
// speedup vs baseline: 3.1887x; 1.2783x over previous
#include <cuda_runtime.h>
#include <math.h>

#define NB    128        // batch (graphs)
#define DD    64         // feature dim
#define N0V   1024       // nodes per graph, layer 0
#define NTOT  (NB*N0V)   // 131072
#define EPG   16384      // edges per graph (contiguous blocks)
#define ETOT  (NB*EPG)   // 2097152
#define KK1   820
#define KK2   656
#define KK3   525

#define INF_F __int_as_float(0x7f800000)

// ---------------- scratch (device globals; no allocations) ----------------
__device__ float g_xb[3][NTOT*DD];     // ping-pong x buffers
__device__ float g_msg[NTOT*DD];
__device__ float g_aggr[NTOT*DD];
__device__ int   g_combo[NTOT];        // layer-1 (id,mask) combo per node
__device__ int   g_inv2[NTOT];         // per-layer inv (current ids)
__device__ int   g_csr[ETOT];
__device__ int   g_rowstart[NTOT];
__device__ int   g_rowcnt[NTOT];
__device__ int   g_invf[NTOT];         // composed: original node -> current id (-1 dropped)
__device__ float g_h[NB*2*DD];
__device__ float g_out2c[64*64];       // layer-1 update table per combo
__device__ float g_scorec[64];         // layer-1 score per combo

__global__ void k_zero_h(float* __restrict__ h)
{
    int i = blockIdx.x * blockDim.x + threadIdx.x;
    if (i < NB*2*DD) h[i] = 0.f;
}

// ---------------- layer-1 tables: 64 combos (id, neighbor-id mask) ----------------
// msg4[id] = relu(emb[id]@W1^T+b1); aggr(c) = max over bits of (mask|1<<id) of msg4;
// out2c[c] = relu([aggr, emb[id]] @ U1^T); scorec[c] = out2c[c]·p1.
__global__ void k_tab1(const float* __restrict__ emb, const float* __restrict__ W1,
                       const float* __restrict__ b1, const float* __restrict__ U1,
                       const float* __restrict__ p1,
                       float* __restrict__ out2c, float* __restrict__ scorec)
{
    __shared__ float smsg[4][64];
    __shared__ float saggr[64][65];
    __shared__ float sout[64][65];
    __shared__ float sp[64];
    int t = threadIdx.x;               // 128 threads
    if (t < 64) {
        sp[t] = p1[t];
        float b = b1[t];
        for (int id = 0; id < 4; id++) {
            float acc = b;
            for (int k = 0; k < 64; k++) acc = fmaf(emb[id*64 + k], W1[t*64 + k], acc);
            smsg[id][t] = fmaxf(acc, 0.f);
        }
    }
    __syncthreads();
    {
        int c = t >> 1, h = t & 1;
        int id = c >> 4;
        int m = (c & 15) | (1 << id);
        for (int k = h*32; k < h*32 + 32; k++) {
            float v = -INF_F;
            #pragma unroll
            for (int b = 0; b < 4; b++)
                if ((m >> b) & 1) v = fmaxf(v, smsg[b][k]);
            saggr[c][k] = v;
        }
    }
    __syncthreads();
    {
        int c = t >> 1, h = t & 1;
        int id = c >> 4;
        for (int o = h*32; o < h*32 + 32; o++) {
            float acc = 0.f;
            for (int k = 0; k < 64; k++) acc = fmaf(saggr[c][k], U1[o*128 + k], acc);
            for (int k = 0; k < 64; k++) acc = fmaf(emb[id*64 + k], U1[o*128 + 64 + k], acc);
            float r = fmaxf(acc, 0.f);
            sout[c][o] = r;
            out2c[c*64 + o] = r;
        }
    }
    __syncthreads();
    if (t < 64) {
        float s = 0.f;
        for (int o = 0; o < 64; o++) s += sout[t][o] * sp[o];
        scorec[t] = s;
    }
}

// ---------------- layer-1 neighbor-id mask per dst (block per graph) ----------------
__global__ void k_mask1(const int* __restrict__ ids, const int* __restrict__ ei,
                        int* __restrict__ combo)
{
    __shared__ int mask[1024];
    int g = blockIdx.x, tid = threadIdx.x;      // 256 threads
    for (int i = tid; i < 1024; i += 256) mask[i] = 0;
    __syncthreads();
    int e0 = g * EPG, nb = g * 1024;
    for (int e = tid; e < EPG; e += 256) {
        int s = ei[e0 + e];
        int d = ei[ETOT + e0 + e];
        atomicOr(&mask[d - nb], 1 << ids[s]);
    }
    __syncthreads();
    for (int i = tid; i < 1024; i += 256)
        combo[nb + i] = (ids[nb + i] << 4) | mask[i];
}

// ---------------- layer-1 TopK from tables (block per graph, 1024 threads) ----------------
__global__ void k_topk1(const int* __restrict__ combo, const float* __restrict__ out2c,
                        const float* __restrict__ scorec, const float* __restrict__ p,
                        float* __restrict__ xnew, int* __restrict__ inv)
{
    __shared__ float sval[1024];
    __shared__ int   sidx[1024];
    __shared__ int   scmb[1024];
    __shared__ float stan[1024];
    __shared__ float stab[64];
    __shared__ float sout[64*64];
    __shared__ float sinv_s;
    int g = blockIdx.x, tid = threadIdx.x;
    if (tid < 64) stab[tid] = scorec[tid];
    for (int i = tid; i < 64*64; i += 1024) sout[i] = out2c[i];
    if (tid == 0) {
        float s = 0.f;
        for (int k = 0; k < 64; k++) { float v = p[k]; s += v*v; }
        sinv_s = 1.f / sqrtf(s);
    }
    int nb = g * 1024;
    scmb[tid] = combo[nb + tid];
    inv[nb + tid] = -1;
    __syncthreads();
    sval[tid] = stab[scmb[tid]];
    sidx[tid] = tid;
    __syncthreads();
    // bitonic sort: descending by value, ascending index on ties
    for (int ksz = 2; ksz <= 1024; ksz <<= 1) {
        for (int j = ksz >> 1; j > 0; j >>= 1) {
            int ixj = tid ^ j;
            if (ixj > tid) {
                float va = sval[tid], vb = sval[ixj];
                int   ia = sidx[tid], ib = sidx[ixj];
                bool a_first = (va > vb) || (va == vb && ia < ib);
                bool descHere = ((tid & ksz) == 0);
                if (descHere != a_first) {
                    sval[tid] = vb; sval[ixj] = va;
                    sidx[tid] = ib; sidx[ixj] = ia;
                }
            }
            __syncthreads();
        }
    }
    if (tid < KK1) {
        inv[nb + sidx[tid]] = g*KK1 + tid;
        stan[tid] = tanhf(sval[tid] * sinv_s);
    }
    __syncthreads();
    for (int idx = tid; idx < KK1*64; idx += 1024) {
        int j = idx >> 6, k = idx & 63;
        int c = scmb[sidx[j]];
        xnew[((size_t)g*KK1 + j)*64 + k] = sout[c*64 + k] * stan[j];
    }
}

// ---------------- GEMM 1: msg = relu(x @ W^T + b), K = 64 (8x8 reg tiles) ----------------
__global__ void __launch_bounds__(128) k_gemm_relu(
        const float* __restrict__ A, const float* __restrict__ W,
        const float* __restrict__ bias, float* __restrict__ out, int nrows)
{
    __shared__ float sW[64][65];
    __shared__ float sAt[64][129];
    __shared__ float sb[64];
    int tid = threadIdx.x;
    for (int idx = tid; idx < 64*64; idx += 128) {
        int o = idx >> 6, k = idx & 63;
        sW[k][o] = W[idx];
    }
    if (tid < 64) sb[tid] = bias[tid];
    size_t row0 = (size_t)blockIdx.x * 128;
    const float* Ab = A + row0 * 64;
    for (int idx = tid; idx < 128*64; idx += 128) {
        int r = idx >> 6, k = idx & 63;
        sAt[k][r] = Ab[idx];
    }
    __syncthreads();
    int tr = tid >> 3;
    int tc = (tid & 7) << 3;
    float acc[8][8];
    #pragma unroll
    for (int i = 0; i < 8; i++)
        #pragma unroll
        for (int j = 0; j < 8; j++) acc[i][j] = sb[tc + j];
    #pragma unroll 4
    for (int k = 0; k < 64; k++) {
        float a[8], w[8];
        #pragma unroll
        for (int i = 0; i < 8; i++) a[i] = sAt[k][tr + 16*i];
        #pragma unroll
        for (int j = 0; j < 8; j++) w[j] = sW[k][tc + j];
        #pragma unroll
        for (int i = 0; i < 8; i++)
            #pragma unroll
            for (int j = 0; j < 8; j++) acc[i][j] = fmaf(a[i], w[j], acc[i][j]);
    }
    #pragma unroll
    for (int i = 0; i < 8; i++) {
        float* o = out + (row0 + tr + 16*i) * 64 + tc;
        #pragma unroll
        for (int j = 0; j < 8; j++) o[j] = fmaxf(acc[i][j], 0.f);
    }
}

// ---------------- GEMM 2: out = relu([aggr, x] @ U^T), K = 128 ----------------
__global__ void __launch_bounds__(128) k_gemm2_relu(
        const float* __restrict__ Agg, const float* __restrict__ X,
        const float* __restrict__ U, float* __restrict__ out, int nrows)
{
    __shared__ float sU[128][65];
    __shared__ float sAt[64][129];
    int tid = threadIdx.x;
    for (int idx = tid; idx < 64*128; idx += 128) {
        int o = idx >> 7, k = idx & 127;
        sU[k][o] = U[idx];
    }
    size_t row0 = (size_t)blockIdx.x * 128;
    int tr = tid >> 3;
    int tc = (tid & 7) << 3;
    float acc[8][8];
    #pragma unroll
    for (int i = 0; i < 8; i++)
        #pragma unroll
        for (int j = 0; j < 8; j++) acc[i][j] = 0.f;
    #pragma unroll
    for (int ph = 0; ph < 2; ph++) {
        const float* Ab = (ph == 0 ? Agg : X) + row0 * 64;
        if (ph) __syncthreads();
        for (int idx = tid; idx < 128*64; idx += 128) {
            int r = idx >> 6, k = idx & 63;
            sAt[k][r] = Ab[idx];
        }
        __syncthreads();
        int kofs = ph << 6;
        #pragma unroll 4
        for (int k = 0; k < 64; k++) {
            float a[8], w[8];
            #pragma unroll
            for (int i = 0; i < 8; i++) a[i] = sAt[k][tr + 16*i];
            #pragma unroll
            for (int j = 0; j < 8; j++) w[j] = sU[kofs + k][tc + j];
            #pragma unroll
            for (int i = 0; i < 8; i++)
                #pragma unroll
                for (int j = 0; j < 8; j++) acc[i][j] = fmaf(a[i], w[j], acc[i][j]);
        }
    }
    #pragma unroll
    for (int i = 0; i < 8; i++) {
        float* o = out + (row0 + tr + 16*i) * 64 + tc;
        #pragma unroll
        for (int j = 0; j < 8; j++) o[j] = fmaxf(acc[i][j], 0.f);
    }
}

// ---------------- CSR from ORIGINAL edges through composed inv (block per graph) ----------------
__global__ void k_csr2(const int* __restrict__ ei, const int* __restrict__ invf, int n,
                       int* __restrict__ rowstart, int* __restrict__ rowcnt,
                       int* __restrict__ csr)
{
    __shared__ int cnt[1024];
    __shared__ int offs[1024];
    __shared__ int part[256];
    int g = blockIdx.x, tid = threadIdx.x;     // 256 threads
    for (int i = tid; i < n; i += 256) cnt[i] = 0;
    __syncthreads();
    int e0 = g * EPG;
    int nb = g * n;
    for (int e = tid; e < EPG; e += 256) {
        int s = invf[ei[e0 + e]];
        if (s < 0) continue;
        int d = invf[ei[ETOT + e0 + e]];
        if (d < 0) continue;
        atomicAdd(&cnt[d - nb], 1);
    }
    __syncthreads();
    int chunk = (n + 255) >> 8;
    int base = tid * chunk;
    int run = 0;
    for (int j = 0; j < chunk; j++) {
        int i = base + j;
        if (i < n) { offs[i] = run; run += cnt[i]; }
    }
    part[tid] = run;
    __syncthreads();
    if (tid == 0) {
        int acc = 0;
        for (int t = 0; t < 256; t++) { int v = part[t]; part[t] = acc; acc += v; }
    }
    __syncthreads();
    int add = part[tid];
    for (int j = 0; j < chunk; j++) {
        int i = base + j;
        if (i < n) offs[i] += add;
    }
    __syncthreads();
    for (int i = tid; i < n; i += 256) {
        rowstart[nb + i] = offs[i];
        rowcnt[nb + i]   = cnt[i];
    }
    __syncthreads();
    for (int e = tid; e < EPG; e += 256) {
        int s = invf[ei[e0 + e]];
        if (s < 0) continue;
        int d = invf[ei[ETOT + e0 + e]];
        if (d < 0) continue;
        int pos = atomicAdd(&offs[d - nb], 1);
        csr[e0 + pos] = s;   // current-layer src id
    }
}

// ---------------- gather-max aggregation (warp per dst node, MLP=4) ----------------
__global__ void k_aggr(const float* __restrict__ msg, const int* __restrict__ rowstart,
                       const int* __restrict__ rowcnt, const int* __restrict__ csr,
                       float* __restrict__ aggr, int n, int n_nodes)
{
    int warp = (blockIdx.x * blockDim.x + threadIdx.x) >> 5;
    int lane = threadIdx.x & 31;
    if (warp >= n_nodes) return;
    const float2* m2 = (const float2*)msg;
    float2 acc = m2[(size_t)warp*32 + lane];            // self-loop init
    int g = warp / n;
    int st = rowstart[warp], c = rowcnt[warp];
    const int* lst = csr + (size_t)g * EPG + st;
    int t = 0;
    for (; t + 4 <= c; t += 4) {
        int s0 = lst[t], s1 = lst[t+1], s2 = lst[t+2], s3 = lst[t+3];
        float2 v0 = m2[(size_t)s0*32 + lane];
        float2 v1 = m2[(size_t)s1*32 + lane];
        float2 v2 = m2[(size_t)s2*32 + lane];
        float2 v3 = m2[(size_t)s3*32 + lane];
        v0.x = fmaxf(v0.x, v1.x); v0.y = fmaxf(v0.y, v1.y);
        v2.x = fmaxf(v2.x, v3.x); v2.y = fmaxf(v2.y, v3.y);
        v0.x = fmaxf(v0.x, v2.x); v0.y = fmaxf(v0.y, v2.y);
        acc.x = fmaxf(acc.x, v0.x); acc.y = fmaxf(acc.y, v0.y);
    }
    for (; t < c; t++) {
        int s = lst[t];
        float2 v = m2[(size_t)s*32 + lane];
        acc.x = fmaxf(acc.x, v.x);
        acc.y = fmaxf(acc.y, v.y);
    }
    ((float2*)aggr)[(size_t)warp*32 + lane] = acc;
}

// ---------------- generic TopK (block per graph, 1024 threads) ----------------
__global__ void k_topk(const float* __restrict__ x, const float* __restrict__ p,
                       int n, int K, float* __restrict__ xnew, int* __restrict__ inv)
{
    __shared__ float sval[1024];
    __shared__ int   sidx[1024];
    __shared__ float stan[1024];
    __shared__ float pp[64];
    __shared__ float sinv;
    int g = blockIdx.x, tid = threadIdx.x;
    if (tid < 64) pp[tid] = p[tid];
    __syncthreads();
    if (tid == 0) {
        float s = 0.f;
        for (int k = 0; k < 64; k++) s += pp[k]*pp[k];
        sinv = 1.f / sqrtf(s);
    }
    int warp = tid >> 5, lane = tid & 31;
    const float2* pv2 = (const float2*)pp;
    for (int i = warp; i < 1024; i += 32) {
        float dsum = 0.f;
        if (i < n) {
            const float2* row = (const float2*)(x + ((size_t)g*n + i)*64);
            float2 a = row[lane];
            float2 b = pv2[lane];
            dsum = a.x*b.x + a.y*b.y;
            #pragma unroll
            for (int o = 16; o > 0; o >>= 1) dsum += __shfl_down_sync(0xffffffffu, dsum, o);
        }
        if (lane == 0) {
            sval[i] = (i < n) ? dsum : -INF_F;
            sidx[i] = i;
        }
    }
    __syncthreads();
    for (int ksz = 2; ksz <= 1024; ksz <<= 1) {
        for (int j = ksz >> 1; j > 0; j >>= 1) {
            int ixj = tid ^ j;
            if (ixj > tid) {
                float va = sval[tid], vb = sval[ixj];
                int   ia = sidx[tid], ib = sidx[ixj];
                bool a_first = (va > vb) || (va == vb && ia < ib);
                bool descHere = ((tid & ksz) == 0);
                if (descHere != a_first) {
                    sval[tid] = vb; sval[ixj] = va;
                    sidx[tid] = ib; sidx[ixj] = ia;
                }
            }
            __syncthreads();
        }
    }
    for (int i = tid; i < n; i += 1024) inv[g*n + i] = -1;
    __syncthreads();
    if (tid < K) {
        inv[g*n + sidx[tid]] = g*K + tid;
        stan[tid] = tanhf(sval[tid] * sinv);
    }
    __syncthreads();
    for (int idx = tid; idx < K*64; idx += 1024) {
        int j = idx >> 6, k = idx & 63;
        xnew[((size_t)g*K + j)*64 + k] = x[((size_t)g*n + sidx[j])*64 + k] * stan[j];
    }
}

// ---------------- compose: invf[orig] = inv2[invf[orig]] ----------------
__global__ void k_compose(int* __restrict__ invf, const int* __restrict__ inv2)
{
    int i = blockIdx.x * blockDim.x + threadIdx.x;
    if (i < NTOT) {
        int t = invf[i];
        invf[i] = (t >= 0) ? inv2[t] : -1;
    }
}

// ---------------- readout: h[g] += [max_k, mean_k] ----------------
__global__ void k_readout(const float* __restrict__ x, int K, float* __restrict__ h)
{
    __shared__ float smx[4][64];
    __shared__ float ssm[4][64];
    int g = blockIdx.x;
    int d = threadIdx.x & 63;
    int part = threadIdx.x >> 6;
    float mx = -INF_F, sm = 0.f;
    const float* base = x + (size_t)g*K*64 + d;
    int j = part;
    for (; j + 16 <= K; j += 16) {
        float v0 = base[(size_t)(j     )*64];
        float v1 = base[(size_t)(j +  4)*64];
        float v2 = base[(size_t)(j +  8)*64];
        float v3 = base[(size_t)(j + 12)*64];
        mx = fmaxf(mx, fmaxf(fmaxf(v0, v1), fmaxf(v2, v3)));
        sm += (v0 + v1) + (v2 + v3);
    }
    for (; j < K; j += 4) {
        float v = base[(size_t)j*64];
        mx = fmaxf(mx, v);
        sm += v;
    }
    smx[part][d] = mx;
    ssm[part][d] = sm;
    __syncthreads();
    if (part == 0) {
        mx = fmaxf(fmaxf(smx[0][d], smx[1][d]), fmaxf(smx[2][d], smx[3][d]));
        sm = (ssm[0][d] + ssm[1][d]) + (ssm[2][d] + ssm[3][d]);
        h[g*128 + d]      += mx;
        h[g*128 + 64 + d] += sm / (float)K;
    }
}

// ---------------- final MLP (block per graph) ----------------
__global__ void k_mlp(const float* __restrict__ h,
                      const float* __restrict__ l1W, const float* __restrict__ l1b,
                      const float* __restrict__ l2W, const float* __restrict__ l2b,
                      const float* __restrict__ l3W, const float* __restrict__ l3b,
                      float* __restrict__ out)
{
    int g = blockIdx.x, o = threadIdx.x;   // 64 threads
    __shared__ float sh[128], t1[64], t2[64];
    sh[o]      = h[g*128 + o];
    sh[64 + o] = h[g*128 + 64 + o];
    __syncthreads();
    float a = l1b[o];
    for (int k = 0; k < 128; k++) a = fmaf(sh[k], l1W[o*128 + k], a);
    t1[o] = fmaxf(a, 0.f);
    __syncthreads();
    float b = l2b[o];
    for (int k = 0; k < 64; k++) b = fmaf(t1[k], l2W[o*64 + k], b);
    t2[o] = fmaxf(b, 0.f);
    __syncthreads();
    float c = l3b[o];
    for (int k = 0; k < 64; k++) c = fmaf(t2[k], l3W[o*64 + k], c);
    out[g*64 + o] = 1.f / (1.f + expf(-c));
}

// ---------------- batch output: repeat(arange(B), K3) ----------------
__global__ void k_batch(float* __restrict__ out, int total)
{
    int i = blockIdx.x * blockDim.x + threadIdx.x;
    if (i < total) out[NB*DD + i] = (float)(i / KK3);
}

// ---------------- host ----------------
extern "C" void kernel_launch(void* const* d_in, const int* in_sizes, int n_in,
                              void* d_out, int out_size)
{
    const int*   x_ids = (const int*)d_in[0];
    const int*   ei    = (const int*)d_in[1];
    const float* emb   = (const float*)d_in[2];
    const float* W[3]  = {(const float*)d_in[3], (const float*)d_in[7],  (const float*)d_in[11]};
    const float* bb[3] = {(const float*)d_in[4], (const float*)d_in[8],  (const float*)d_in[12]};
    const float* U[3]  = {(const float*)d_in[5], (const float*)d_in[9],  (const float*)d_in[13]};
    const float* p[3]  = {(const float*)d_in[6], (const float*)d_in[10], (const float*)d_in[14]};
    const float* l1W = (const float*)d_in[15];
    const float* l1b = (const float*)d_in[16];
    const float* l2W = (const float*)d_in[17];
    const float* l2b = (const float*)d_in[18];
    const float* l3W = (const float*)d_in[19];
    const float* l3b = (const float*)d_in[20];

    float *xbase, *msg, *aggr, *h, *out2c, *scorec;
    int *combo, *inv2, *csr, *rowstart, *rowcnt, *invf;
    cudaGetSymbolAddress((void**)&xbase,    g_xb);
    cudaGetSymbolAddress((void**)&msg,      g_msg);
    cudaGetSymbolAddress((void**)&aggr,     g_aggr);
    cudaGetSymbolAddress((void**)&combo,    g_combo);
    cudaGetSymbolAddress((void**)&inv2,     g_inv2);
    cudaGetSymbolAddress((void**)&csr,      g_csr);
    cudaGetSymbolAddress((void**)&rowstart, g_rowstart);
    cudaGetSymbolAddress((void**)&rowcnt,   g_rowcnt);
    cudaGetSymbolAddress((void**)&invf,     g_invf);
    cudaGetSymbolAddress((void**)&h,        g_h);
    cudaGetSymbolAddress((void**)&out2c,    g_out2c);
    cudaGetSymbolAddress((void**)&scorec,   g_scorec);

    float* xs0 = xbase;
    float* xs1 = xbase + (size_t)NTOT*DD;
    float* xs2 = xbase + (size_t)2*NTOT*DD;

    k_zero_h<<<(NB*2*DD + 255)/256, 256>>>(h);

    // ---- layer 1 via tables (4 distinct embeddings -> 64 combos) ----
    k_tab1<<<1, 128>>>(emb, W[0], bb[0], U[0], p[0], out2c, scorec);
    k_mask1<<<NB, 256>>>(x_ids, ei, combo);
    k_topk1<<<NB, 1024>>>(combo, out2c, scorec, p[0], xs0, invf);
    k_readout<<<NB, 256>>>(xs0, KK1, h);

    // ---- layer 2 ----
    {
        int n = KK1, K = KK2, nrows = NB * KK1;
        k_gemm_relu<<<nrows/128, 128>>>(xs0, W[1], bb[1], msg, nrows);
        k_csr2<<<NB, 256>>>(ei, invf, n, rowstart, rowcnt, csr);
        k_aggr<<<(nrows + 7)/8, 256>>>(msg, rowstart, rowcnt, csr, aggr, n, nrows);
        k_gemm2_relu<<<nrows/128, 128>>>(aggr, xs0, U[1], xs1, nrows);
        k_topk<<<NB, 1024>>>(xs1, p[1], n, K, xs2, inv2);
        k_compose<<<(NTOT + 255)/256, 256>>>(invf, inv2);
        k_readout<<<NB, 256>>>(xs2, K, h);
    }

    // ---- layer 3 ----
    {
        int n = KK2, K = KK3, nrows = NB * KK2;
        k_gemm_relu<<<nrows/128, 128>>>(xs2, W[2], bb[2], msg, nrows);
        k_csr2<<<NB, 256>>>(ei, invf, n, rowstart, rowcnt, csr);
        k_aggr<<<(nrows + 7)/8, 256>>>(msg, rowstart, rowcnt, csr, aggr, n, nrows);
        k_gemm2_relu<<<nrows/128, 128>>>(aggr, xs2, U[2], xs0, nrows);
        k_topk<<<NB, 1024>>>(xs0, p[2], n, K, xs1, inv2);   // inv unused after layer 3
        k_readout<<<NB, 256>>>(xs1, K, h);
    }

    k_mlp<<<NB, 64>>>(h, l1W, l1b, l2W, l2b, l3W, l3b, (float*)d_out);

    if (out_size > NB*DD) {
        int total = out_size - NB*DD;
        k_batch<<<(total + 255)/256, 256>>>((float*)d_out, total);
    }
}

// round 7
// speedup vs baseline: 3.9917x; 1.2518x over previous
#include <cuda_runtime.h>
#include <math.h>

#define NB    128        // batch (graphs)
#define DD    64         // feature dim
#define N0V   1024       // nodes per graph, layer 0
#define NTOT  (NB*N0V)   // 131072
#define EPG   16384      // edges per graph (contiguous blocks)
#define ETOT  (NB*EPG)   // 2097152
#define KK1   820
#define KK2   656
#define KK3   525

#define INF_F __int_as_float(0x7f800000)

// ---------------- scratch (device globals; no allocations) ----------------
__device__ float g_xb[3][NTOT*DD];     // ping-pong x buffers
__device__ float g_msg[NTOT*DD];
__device__ float g_aggr[NTOT*DD];
__device__ float g_score[NTOT];        // per-row score (from gemm2 epilogue)
__device__ int   g_inv2[NTOT];         // per-layer inv (current ids)
__device__ int   g_invf[NTOT];         // composed: original node -> current id (-1 dropped)
__device__ float g_h[NB*2*DD];
__device__ float g_out2c[64*64];       // layer-1 update table per combo
__device__ float g_scorec[64];         // layer-1 score per combo

__global__ void k_zero_h(float* __restrict__ h)
{
    int i = blockIdx.x * blockDim.x + threadIdx.x;
    if (i < NB*2*DD) h[i] = 0.f;
}

// ---------------- hybrid bitonic sort: 1024 elems, regs + shfl for j<32 ----------------
// Descending by value, ascending index on ties (matches jax.lax.top_k).
__device__ __forceinline__ void bitonic1024(float& v, int& i, float* sval, int* sidx, int tid)
{
    for (int ksz = 2; ksz <= 1024; ksz <<= 1) {
        for (int j = ksz >> 1; j > 0; j >>= 1) {
            bool descHere = ((tid & ksz) == 0);
            bool lower    = ((tid & j) == 0);
            float vp; int ip;
            if (j >= 32) {
                sval[tid] = v; sidx[tid] = i;
                __syncthreads();
                vp = sval[tid ^ j]; ip = sidx[tid ^ j];
                __syncthreads();
            } else {
                vp = __shfl_xor_sync(0xffffffffu, v, j);
                ip = __shfl_xor_sync(0xffffffffu, i, j);
            }
            float vlo = lower ? v : vp;  int ilo = lower ? i : ip;
            float vhi = lower ? vp : v;  int ihi = lower ? ip : i;
            bool a_first = (vlo > vhi) || (vlo == vhi && ilo < ihi);
            if (descHere != a_first) { v = vp; i = ip; }
        }
    }
    sval[tid] = v; sidx[tid] = i;
    __syncthreads();
}

// ---------------- layer-1 tables: 64 combos (id, neighbor-id mask) ----------------
__global__ void k_tab1(const float* __restrict__ emb, const float* __restrict__ W1,
                       const float* __restrict__ b1, const float* __restrict__ U1,
                       const float* __restrict__ p1,
                       float* __restrict__ out2c, float* __restrict__ scorec)
{
    __shared__ float smsg[4][64];
    __shared__ float saggr[64][65];
    __shared__ float sout[64][65];
    __shared__ float sp[64];
    int t = threadIdx.x;               // 128 threads
    if (t < 64) {
        sp[t] = p1[t];
        float b = b1[t];
        for (int id = 0; id < 4; id++) {
            float acc = b;
            for (int k = 0; k < 64; k++) acc = fmaf(emb[id*64 + k], W1[t*64 + k], acc);
            smsg[id][t] = fmaxf(acc, 0.f);
        }
    }
    __syncthreads();
    {
        int c = t >> 1, h = t & 1;
        int id = c >> 4;
        int m = (c & 15) | (1 << id);
        for (int k = h*32; k < h*32 + 32; k++) {
            float v = -INF_F;
            #pragma unroll
            for (int b = 0; b < 4; b++)
                if ((m >> b) & 1) v = fmaxf(v, smsg[b][k]);
            saggr[c][k] = v;
        }
    }
    __syncthreads();
    {
        int c = t >> 1, h = t & 1;
        int id = c >> 4;
        for (int o = h*32; o < h*32 + 32; o++) {
            float acc = 0.f;
            for (int k = 0; k < 64; k++) acc = fmaf(saggr[c][k], U1[o*128 + k], acc);
            for (int k = 0; k < 64; k++) acc = fmaf(emb[id*64 + k], U1[o*128 + 64 + k], acc);
            float r = fmaxf(acc, 0.f);
            sout[c][o] = r;
            out2c[c*64 + o] = r;
        }
    }
    __syncthreads();
    if (t < 64) {
        float s = 0.f;
        for (int o = 0; o < 64; o++) s += sout[t][o] * sp[o];
        scorec[t] = s;
    }
}

// ---------------- layer-1: mask build + topk + xnew + readout, all in one ----------------
__global__ void __launch_bounds__(1024) k_topk1(
        const int* __restrict__ ids, const int* __restrict__ ei,
        const float* __restrict__ out2c, const float* __restrict__ scorec,
        const float* __restrict__ p,
        float* __restrict__ xnew, int* __restrict__ invf, float* __restrict__ h)
{
    __shared__ int   sids[1024];
    __shared__ int   smask[1024];
    __shared__ float sval[1024];
    __shared__ int   sidx[1024];
    __shared__ float stan[KK1];
    __shared__ float stab[64];
    __shared__ float sout[64*64];
    __shared__ float smx[16][64];
    __shared__ float ssm[16][64];
    __shared__ float sinv_s;
    int g = blockIdx.x, tid = threadIdx.x;
    int nb = g * 1024;
    sids[tid]  = ids[nb + tid];
    smask[tid] = 0;
    if (tid < 64) stab[tid] = scorec[tid];
    for (int i = tid; i < 64*64; i += 1024) sout[i] = out2c[i];
    if (tid == 0) {
        float s = 0.f;
        for (int k = 0; k < 64; k++) { float v = p[k]; s += v*v; }
        sinv_s = 1.f / sqrtf(s);
    }
    __syncthreads();
    int e0 = g * EPG;
    for (int e = tid; e < EPG; e += 1024) {
        int s = ei[e0 + e] - nb;
        int d = ei[ETOT + e0 + e] - nb;
        atomicOr(&smask[d], 1 << sids[s]);
    }
    invf[nb + tid] = -1;
    __syncthreads();
    float v = stab[(sids[tid] << 4) | smask[tid]];
    int   ix = tid;
    bitonic1024(v, ix, sval, sidx, tid);
    if (tid < KK1) {
        invf[nb + sidx[tid]] = g*KK1 + tid;
        stan[tid] = tanhf(sval[tid] * sinv_s);
    }
    __syncthreads();
    float mx = -INF_F, sm = 0.f;
    for (int idx = tid; idx < KK1*64; idx += 1024) {
        int j = idx >> 6, k = idx & 63;
        int node = sidx[j];
        int c = (sids[node] << 4) | smask[node];
        float val = sout[c*64 + k] * stan[j];
        xnew[((size_t)g*KK1 + j)*64 + k] = val;
        mx = fmaxf(mx, val); sm += val;
    }
    int part = tid >> 6, d = tid & 63;
    smx[part][d] = mx; ssm[part][d] = sm;
    __syncthreads();
    if (tid < 64) {
        float m = smx[0][tid], s = ssm[0][tid];
        #pragma unroll
        for (int t2 = 1; t2 < 16; t2++) { m = fmaxf(m, smx[t2][tid]); s += ssm[t2][tid]; }
        h[g*128 + tid]      += m;
        h[g*128 + 64 + tid] += s / (float)KK1;
    }
}

// ---------------- GEMM 1: msg = relu(x @ W^T + b), K = 64 (8x8 reg tiles) ----------------
__global__ void __launch_bounds__(128) k_gemm_relu(
        const float* __restrict__ A, const float* __restrict__ W,
        const float* __restrict__ bias, float* __restrict__ out, int nrows)
{
    __shared__ float sW[64][65];
    __shared__ float sAt[64][129];
    __shared__ float sb[64];
    int tid = threadIdx.x;
    for (int idx = tid; idx < 64*64; idx += 128) {
        int o = idx >> 6, k = idx & 63;
        sW[k][o] = W[idx];
    }
    if (tid < 64) sb[tid] = bias[tid];
    size_t row0 = (size_t)blockIdx.x * 128;
    const float* Ab = A + row0 * 64;
    for (int idx = tid; idx < 128*64; idx += 128) {
        int r = idx >> 6, k = idx & 63;
        sAt[k][r] = Ab[idx];
    }
    __syncthreads();
    int tr = tid >> 3;
    int tc = (tid & 7) << 3;
    float acc[8][8];
    #pragma unroll
    for (int i = 0; i < 8; i++)
        #pragma unroll
        for (int j = 0; j < 8; j++) acc[i][j] = sb[tc + j];
    #pragma unroll 4
    for (int k = 0; k < 64; k++) {
        float a[8], w[8];
        #pragma unroll
        for (int i = 0; i < 8; i++) a[i] = sAt[k][tr + 16*i];
        #pragma unroll
        for (int j = 0; j < 8; j++) w[j] = sW[k][tc + j];
        #pragma unroll
        for (int i = 0; i < 8; i++)
            #pragma unroll
            for (int j = 0; j < 8; j++) acc[i][j] = fmaf(a[i], w[j], acc[i][j]);
    }
    #pragma unroll
    for (int i = 0; i < 8; i++) {
        float* o = out + (row0 + tr + 16*i) * 64 + tc;
        #pragma unroll
        for (int j = 0; j < 8; j++) o[j] = fmaxf(acc[i][j], 0.f);
    }
}

// ---------------- GEMM 2 + score: out = relu([aggr, x] @ U^T); score = out·p ----------------
__global__ void __launch_bounds__(128) k_gemm2_relu(
        const float* __restrict__ Agg, const float* __restrict__ X,
        const float* __restrict__ U, const float* __restrict__ p,
        float* __restrict__ out, float* __restrict__ score, int nrows)
{
    __shared__ float sU[128][65];
    __shared__ float sAt[64][129];
    __shared__ float sp[64];
    int tid = threadIdx.x;
    for (int idx = tid; idx < 64*128; idx += 128) {
        int o = idx >> 7, k = idx & 127;
        sU[k][o] = U[idx];
    }
    if (tid < 64) sp[tid] = p[tid];
    size_t row0 = (size_t)blockIdx.x * 128;
    int tr = tid >> 3;
    int tc = (tid & 7) << 3;
    float acc[8][8];
    #pragma unroll
    for (int i = 0; i < 8; i++)
        #pragma unroll
        for (int j = 0; j < 8; j++) acc[i][j] = 0.f;
    #pragma unroll
    for (int ph = 0; ph < 2; ph++) {
        const float* Ab = (ph == 0 ? Agg : X) + row0 * 64;
        if (ph) __syncthreads();
        for (int idx = tid; idx < 128*64; idx += 128) {
            int r = idx >> 6, k = idx & 63;
            sAt[k][r] = Ab[idx];
        }
        __syncthreads();
        int kofs = ph << 6;
        #pragma unroll 4
        for (int k = 0; k < 64; k++) {
            float a[8], w[8];
            #pragma unroll
            for (int i = 0; i < 8; i++) a[i] = sAt[k][tr + 16*i];
            #pragma unroll
            for (int j = 0; j < 8; j++) w[j] = sU[kofs + k][tc + j];
            #pragma unroll
            for (int i = 0; i < 8; i++)
                #pragma unroll
                for (int j = 0; j < 8; j++) acc[i][j] = fmaf(a[i], w[j], acc[i][j]);
        }
    }
    #pragma unroll
    for (int i = 0; i < 8; i++) {
        float* o = out + (row0 + tr + 16*i) * 64 + tc;
        float part = 0.f;
        #pragma unroll
        for (int j = 0; j < 8; j++) {
            float r = fmaxf(acc[i][j], 0.f);
            o[j] = r;
            part = fmaf(r, sp[tc + j], part);
        }
        part += __shfl_xor_sync(0xffffffffu, part, 1);
        part += __shfl_xor_sync(0xffffffffu, part, 2);
        part += __shfl_xor_sync(0xffffffffu, part, 4);
        if ((tid & 7) == 0) score[row0 + tr + 16*i] = part;
    }
}

// ---------------- fused CSR-build + gather-max aggregation (block per graph) ----------------
// CSR lives entirely in dynamic smem; invf slice staged in smem.
#define SMEM_CA ((3104 + EPG) * 4)
__global__ void __launch_bounds__(1024) k_csr_aggr(
        const int* __restrict__ ei, const int* __restrict__ invf,
        const float* __restrict__ msg, float* __restrict__ aggr, int n)
{
    extern __shared__ int smem[];
    int* slocal = smem;           // [1024] orig-local -> cur-local (-1 dead)
    int* scnt   = smem + 1024;    // [1024]
    int* scur   = smem + 2048;    // [1024] exclusive prefix -> running cursor
    int* swsum  = smem + 3072;    // [32]
    int* scsr   = smem + 3104;    // [EPG]
    int g = blockIdx.x, tid = threadIdx.x;
    int nb = g * N0V;
    {
        int t = invf[nb + tid];
        slocal[tid] = (t >= 0) ? (t - g*n) : -1;
        scnt[tid] = 0;
    }
    __syncthreads();
    int e0 = g * EPG;
    for (int e = tid; e < EPG; e += 1024) {
        int s = slocal[ei[e0 + e] - nb];
        int d = slocal[ei[ETOT + e0 + e] - nb];
        if ((s | d) >= 0) atomicAdd(&scnt[d], 1);
    }
    __syncthreads();
    {   // exclusive block scan of scnt into scur
        int lane = tid & 31, wid = tid >> 5;
        int v = scnt[tid];
        int x = v;
        #pragma unroll
        for (int o = 1; o < 32; o <<= 1) {
            int t = __shfl_up_sync(0xffffffffu, x, o);
            if (lane >= o) x += t;
        }
        if (lane == 31) swsum[wid] = x;
        __syncthreads();
        if (wid == 0) {
            int w = swsum[lane];
            int y = w;
            #pragma unroll
            for (int o = 1; o < 32; o <<= 1) {
                int t = __shfl_up_sync(0xffffffffu, y, o);
                if (lane >= o) y += t;
            }
            swsum[lane] = y - w;          // exclusive warp prefix
        }
        __syncthreads();
        scur[tid] = x - v + swsum[wid];   // exclusive prefix
    }
    __syncthreads();
    for (int e = tid; e < EPG; e += 1024) {
        int s = slocal[ei[e0 + e] - nb];
        int d = slocal[ei[ETOT + e0 + e] - nb];
        if ((s | d) >= 0) {
            int pos = atomicAdd(&scur[d], 1);
            scsr[pos] = s;
        }
    }
    __syncthreads();
    // aggregate: warp per node; after scatter, scur[i] = end, start = end - cnt
    const float2* m2 = (const float2*)msg;
    int lane = tid & 31, w = tid >> 5;
    for (int i = w; i < n; i += 32) {
        int node = g*n + i;
        float2 acc = m2[(size_t)node*32 + lane];      // self-loop init
        int end = scur[i];
        int t = end - scnt[i];
        for (; t + 4 <= end; t += 4) {
            int s0 = scsr[t], s1 = scsr[t+1], s2 = scsr[t+2], s3 = scsr[t+3];
            float2 v0 = m2[(size_t)(g*n + s0)*32 + lane];
            float2 v1 = m2[(size_t)(g*n + s1)*32 + lane];
            float2 v2 = m2[(size_t)(g*n + s2)*32 + lane];
            float2 v3 = m2[(size_t)(g*n + s3)*32 + lane];
            v0.x = fmaxf(v0.x, v1.x); v0.y = fmaxf(v0.y, v1.y);
            v2.x = fmaxf(v2.x, v3.x); v2.y = fmaxf(v2.y, v3.y);
            v0.x = fmaxf(v0.x, v2.x); v0.y = fmaxf(v0.y, v2.y);
            acc.x = fmaxf(acc.x, v0.x); acc.y = fmaxf(acc.y, v0.y);
        }
        for (; t < end; t++) {
            float2 vv = m2[(size_t)(g*n + scsr[t])*32 + lane];
            acc.x = fmaxf(acc.x, vv.x); acc.y = fmaxf(acc.y, vv.y);
        }
        ((float2*)aggr)[(size_t)node*32 + lane] = acc;
    }
}

// ---------------- generic TopK + xnew + readout (layers 2/3) ----------------
__global__ void __launch_bounds__(1024) k_topk(
        const float* __restrict__ x, const float* __restrict__ score,
        const float* __restrict__ p, int n, int K,
        float* __restrict__ xnew, int* __restrict__ inv, float* __restrict__ h)
{
    __shared__ float sval[1024];
    __shared__ int   sidx[1024];
    __shared__ float stan[672];    // K <= 656 here
    __shared__ float smx[16][64];
    __shared__ float ssm[16][64];
    __shared__ float sinv_s;
    int g = blockIdx.x, tid = threadIdx.x;
    if (tid == 0) {
        float s = 0.f;
        for (int k = 0; k < 64; k++) { float v = p[k]; s += v*v; }
        sinv_s = 1.f / sqrtf(s);
    }
    float v = (tid < n) ? score[(size_t)g*n + tid] : -INF_F;
    int   ix = tid;
    if (tid < n) inv[g*n + tid] = -1;
    bitonic1024(v, ix, sval, sidx, tid);
    if (tid < K) {
        inv[g*n + sidx[tid]] = g*K + tid;
        stan[tid] = tanhf(sval[tid] * sinv_s);
    }
    __syncthreads();
    float mx = -INF_F, sm = 0.f;
    for (int idx = tid; idx < K*64; idx += 1024) {
        int j = idx >> 6, k = idx & 63;
        float val = x[((size_t)g*n + sidx[j])*64 + k] * stan[j];
        xnew[((size_t)g*K + j)*64 + k] = val;
        mx = fmaxf(mx, val); sm += val;
    }
    int part = tid >> 6, d = tid & 63;
    smx[part][d] = mx; ssm[part][d] = sm;
    __syncthreads();
    if (tid < 64) {
        float m = smx[0][tid], s = ssm[0][tid];
        #pragma unroll
        for (int t2 = 1; t2 < 16; t2++) { m = fmaxf(m, smx[t2][tid]); s += ssm[t2][tid]; }
        h[g*128 + tid]      += m;
        h[g*128 + 64 + tid] += s / (float)K;
    }
}

// ---------------- compose: invf[orig] = inv2[invf[orig]] ----------------
__global__ void k_compose(int* __restrict__ invf, const int* __restrict__ inv2)
{
    int i = blockIdx.x * blockDim.x + threadIdx.x;
    if (i < NTOT) {
        int t = invf[i];
        invf[i] = (t >= 0) ? inv2[t] : -1;
    }
}

// ---------------- final MLP (block per graph) ----------------
__global__ void k_mlp(const float* __restrict__ h,
                      const float* __restrict__ l1W, const float* __restrict__ l1b,
                      const float* __restrict__ l2W, const float* __restrict__ l2b,
                      const float* __restrict__ l3W, const float* __restrict__ l3b,
                      float* __restrict__ out)
{
    int g = blockIdx.x, o = threadIdx.x;   // 64 threads
    __shared__ float sh[128], t1[64], t2[64];
    sh[o]      = h[g*128 + o];
    sh[64 + o] = h[g*128 + 64 + o];
    __syncthreads();
    float a = l1b[o];
    for (int k = 0; k < 128; k++) a = fmaf(sh[k], l1W[o*128 + k], a);
    t1[o] = fmaxf(a, 0.f);
    __syncthreads();
    float b = l2b[o];
    for (int k = 0; k < 64; k++) b = fmaf(t1[k], l2W[o*64 + k], b);
    t2[o] = fmaxf(b, 0.f);
    __syncthreads();
    float c = l3b[o];
    for (int k = 0; k < 64; k++) c = fmaf(t2[k], l3W[o*64 + k], c);
    out[g*64 + o] = 1.f / (1.f + expf(-c));
}

// ---------------- batch output: repeat(arange(B), K3) ----------------
__global__ void k_batch(float* __restrict__ out, int total)
{
    int i = blockIdx.x * blockDim.x + threadIdx.x;
    if (i < total) out[NB*DD + i] = (float)(i / KK3);
}

// ---------------- host ----------------
extern "C" void kernel_launch(void* const* d_in, const int* in_sizes, int n_in,
                              void* d_out, int out_size)
{
    const int*   x_ids = (const int*)d_in[0];
    const int*   ei    = (const int*)d_in[1];
    const float* emb   = (const float*)d_in[2];
    const float* W[3]  = {(const float*)d_in[3], (const float*)d_in[7],  (const float*)d_in[11]};
    const float* bb[3] = {(const float*)d_in[4], (const float*)d_in[8],  (const float*)d_in[12]};
    const float* U[3]  = {(const float*)d_in[5], (const float*)d_in[9],  (const float*)d_in[13]};
    const float* p[3]  = {(const float*)d_in[6], (const float*)d_in[10], (const float*)d_in[14]};
    const float* l1W = (const float*)d_in[15];
    const float* l1b = (const float*)d_in[16];
    const float* l2W = (const float*)d_in[17];
    const float* l2b = (const float*)d_in[18];
    const float* l3W = (const float*)d_in[19];
    const float* l3b = (const float*)d_in[20];

    float *xbase, *msg, *aggr, *h, *out2c, *scorec, *score;
    int *inv2, *invf;
    cudaGetSymbolAddress((void**)&xbase,  g_xb);
    cudaGetSymbolAddress((void**)&msg,    g_msg);
    cudaGetSymbolAddress((void**)&aggr,   g_aggr);
    cudaGetSymbolAddress((void**)&score,  g_score);
    cudaGetSymbolAddress((void**)&inv2,   g_inv2);
    cudaGetSymbolAddress((void**)&invf,   g_invf);
    cudaGetSymbolAddress((void**)&h,      g_h);
    cudaGetSymbolAddress((void**)&out2c,  g_out2c);
    cudaGetSymbolAddress((void**)&scorec, g_scorec);

    static int smem_set = 0;
    if (!smem_set) {
        cudaFuncSetAttribute(k_csr_aggr, cudaFuncAttributeMaxDynamicSharedMemorySize, SMEM_CA);
        smem_set = 1;
    }

    float* xs0 = xbase;
    float* xs1 = xbase + (size_t)NTOT*DD;
    float* xs2 = xbase + (size_t)2*NTOT*DD;

    k_zero_h<<<(NB*2*DD + 255)/256, 256>>>(h);

    // ---- layer 1 via tables (4 distinct embeddings -> 64 combos) ----
    k_tab1<<<1, 128>>>(emb, W[0], bb[0], U[0], p[0], out2c, scorec);
    k_topk1<<<NB, 1024>>>(x_ids, ei, out2c, scorec, p[0], xs0, invf, h);

    // ---- layer 2 ----
    {
        int n = KK1, K = KK2, nrows = NB * KK1;
        k_gemm_relu<<<nrows/128, 128>>>(xs0, W[1], bb[1], msg, nrows);
        k_csr_aggr<<<NB, 1024, SMEM_CA>>>(ei, invf, msg, aggr, n);
        k_gemm2_relu<<<nrows/128, 128>>>(aggr, xs0, U[1], p[1], xs1, score, nrows);
        k_topk<<<NB, 1024>>>(xs1, score, p[1], n, K, xs2, inv2, h);
        k_compose<<<(NTOT + 255)/256, 256>>>(invf, inv2);
    }

    // ---- layer 3 ----
    {
        int n = KK2, K = KK3, nrows = NB * KK2;
        k_gemm_relu<<<nrows/128, 128>>>(xs2, W[2], bb[2], msg, nrows);
        k_csr_aggr<<<NB, 1024, SMEM_CA>>>(ei, invf, msg, aggr, n);
        k_gemm2_relu<<<nrows/128, 128>>>(aggr, xs2, U[2], p[2], xs0, score, nrows);
        k_topk<<<NB, 1024>>>(xs0, score, p[2], n, K, xs1, inv2, h);
    }

    k_mlp<<<NB, 64>>>(h, l1W, l1b, l2W, l2b, l3W, l3b, (float*)d_out);

    if (out_size > NB*DD) {
        int total = out_size - NB*DD;
        k_batch<<<(total + 255)/256, 256>>>((float*)d_out, total);
    }
}

// round 10
// speedup vs baseline: 4.1972x; 1.0515x over previous
#include <cuda_runtime.h>
#include <math.h>

#define NB    128        // batch (graphs)
#define DD    64         // feature dim
#define N0V   1024       // nodes per graph, layer 0
#define NTOT  (NB*N0V)   // 131072
#define EPG   16384      // edges per graph (contiguous blocks)
#define ETOT  (NB*EPG)   // 2097152
#define KK1   820
#define KK2   656
#define KK3   525

#define INF_F __int_as_float(0x7f800000)

// ---------------- scratch (device globals; no allocations) ----------------
__device__ float g_xb[3][NTOT*DD];     // ping-pong x buffers
__device__ float g_msg[NTOT*DD];
__device__ float g_aggr[NTOT*DD];
__device__ float g_score[NTOT];        // per-row score (from gemm2 epilogue)
__device__ int   g_invf[NTOT];         // composed: original node -> current id (-1 dropped)
__device__ float g_h[NB*2*DD];
__device__ float g_out2c[64*64];       // layer-1 update table per combo
__device__ float g_scorec[64];         // layer-1 score per combo

// ---------------- hybrid bitonic sort: 1024 elems, regs + shfl for j<32 ----------------
// Descending by value, ascending index on ties (matches jax.lax.top_k).
__device__ __forceinline__ void bitonic1024(float& v, int& i, float* sval, int* sidx, int tid)
{
    for (int ksz = 2; ksz <= 1024; ksz <<= 1) {
        for (int j = ksz >> 1; j > 0; j >>= 1) {
            bool descHere = ((tid & ksz) == 0);
            bool lower    = ((tid & j) == 0);
            float vp; int ip;
            if (j >= 32) {
                sval[tid] = v; sidx[tid] = i;
                __syncthreads();
                vp = sval[tid ^ j]; ip = sidx[tid ^ j];
                __syncthreads();
            } else {
                vp = __shfl_xor_sync(0xffffffffu, v, j);
                ip = __shfl_xor_sync(0xffffffffu, i, j);
            }
            float vlo = lower ? v : vp;  int ilo = lower ? i : ip;
            float vhi = lower ? vp : v;  int ihi = lower ? ip : i;
            bool a_first = (vlo > vhi) || (vlo == vhi && ilo < ihi);
            if (descHere != a_first) { v = vp; i = ip; }
        }
    }
    sval[tid] = v; sidx[tid] = i;
    __syncthreads();
}

// ---------------- layer-1 tables: 64 combos (id, neighbor-id mask) ----------------
__global__ void k_tab1(const float* __restrict__ emb, const float* __restrict__ W1,
                       const float* __restrict__ b1, const float* __restrict__ U1,
                       const float* __restrict__ p1,
                       float* __restrict__ out2c, float* __restrict__ scorec)
{
    __shared__ float smsg[4][64];
    __shared__ float saggr[64][65];
    __shared__ float sout[64][65];
    __shared__ float sp[64];
    int t = threadIdx.x;               // 128 threads
    if (t < 64) {
        sp[t] = p1[t];
        float b = b1[t];
        for (int id = 0; id < 4; id++) {
            float acc = b;
            for (int k = 0; k < 64; k++) acc = fmaf(emb[id*64 + k], W1[t*64 + k], acc);
            smsg[id][t] = fmaxf(acc, 0.f);
        }
    }
    __syncthreads();
    {
        int c = t >> 1, h = t & 1;
        int id = c >> 4;
        int m = (c & 15) | (1 << id);
        for (int k = h*32; k < h*32 + 32; k++) {
            float v = -INF_F;
            #pragma unroll
            for (int b = 0; b < 4; b++)
                if ((m >> b) & 1) v = fmaxf(v, smsg[b][k]);
            saggr[c][k] = v;
        }
    }
    __syncthreads();
    {
        int c = t >> 1, h = t & 1;
        int id = c >> 4;
        for (int o = h*32; o < h*32 + 32; o++) {
            float acc = 0.f;
            for (int k = 0; k < 64; k++) acc = fmaf(saggr[c][k], U1[o*128 + k], acc);
            for (int k = 0; k < 64; k++) acc = fmaf(emb[id*64 + k], U1[o*128 + 64 + k], acc);
            float r = fmaxf(acc, 0.f);
            sout[c][o] = r;
            out2c[c*64 + o] = r;
        }
    }
    __syncthreads();
    if (t < 64) {
        float s = 0.f;
        for (int o = 0; o < 64; o++) s += sout[t][o] * sp[o];
        scorec[t] = s;
    }
}

// ---------------- layer-1: mask build + topk + xnew + readout (h ASSIGNED here) ----------------
__global__ void __launch_bounds__(1024) k_topk1(
        const int* __restrict__ ids, const int* __restrict__ ei,
        const float* __restrict__ out2c, const float* __restrict__ scorec,
        const float* __restrict__ p,
        float* __restrict__ xnew, int* __restrict__ invf, float* __restrict__ h)
{
    __shared__ int   sids[1024];
    __shared__ int   smask[1024];
    __shared__ float sval[1024];
    __shared__ int   sidx[1024];
    __shared__ float stan[KK1];
    __shared__ float stab[64];
    __shared__ float sout[64*64];
    __shared__ float smx[16][64];
    __shared__ float ssm[16][64];
    __shared__ float sinv_s;
    int g = blockIdx.x, tid = threadIdx.x;
    int nb = g * 1024;
    sids[tid]  = ids[nb + tid];
    smask[tid] = 0;
    if (tid < 64) stab[tid] = scorec[tid];
    for (int i = tid; i < 64*64; i += 1024) sout[i] = out2c[i];
    if (tid == 0) {
        float s = 0.f;
        for (int k = 0; k < 64; k++) { float v = p[k]; s += v*v; }
        sinv_s = 1.f / sqrtf(s);
    }
    __syncthreads();
    int e0 = g * EPG;
    for (int e = tid; e < EPG; e += 1024) {
        int s = ei[e0 + e] - nb;
        int d = ei[ETOT + e0 + e] - nb;
        atomicOr(&smask[d], 1 << sids[s]);
    }
    invf[nb + tid] = -1;
    __syncthreads();
    float v = stab[(sids[tid] << 4) | smask[tid]];
    int   ix = tid;
    bitonic1024(v, ix, sval, sidx, tid);
    if (tid < KK1) {
        invf[nb + sidx[tid]] = g*KK1 + tid;
        stan[tid] = tanhf(sval[tid] * sinv_s);
    }
    __syncthreads();
    float mx = -INF_F, sm = 0.f;
    for (int idx = tid; idx < KK1*64; idx += 1024) {
        int j = idx >> 6, k = idx & 63;
        int node = sidx[j];
        int c = (sids[node] << 4) | smask[node];
        float val = sout[c*64 + k] * stan[j];
        xnew[((size_t)g*KK1 + j)*64 + k] = val;
        mx = fmaxf(mx, val); sm += val;
    }
    int part = tid >> 6, d = tid & 63;
    smx[part][d] = mx; ssm[part][d] = sm;
    __syncthreads();
    if (tid < 64) {
        float m = smx[0][tid], s = ssm[0][tid];
        #pragma unroll
        for (int t2 = 1; t2 < 16; t2++) { m = fmaxf(m, smx[t2][tid]); s += ssm[t2][tid]; }
        h[g*128 + tid]      = m;                 // first layer: assign (no zero-kernel)
        h[g*128 + 64 + tid] = s / (float)KK1;
    }
}

// ---------------- GEMM 1: msg = relu(x @ W^T + b), K = 64 ----------------
// Row-major padded A tile (stride 68 floats): coalesced LDG.128 in, LDS.128 W reads,
// broadcast scalar A reads (banks 4*tr+k, conflict-free).
__global__ void __launch_bounds__(128) k_gemm_relu(
        const float* __restrict__ A, const float* __restrict__ W,
        const float* __restrict__ bias, float* __restrict__ out, int nrows)
{
    __shared__ float sW[64][68];    // sW[k][o] = W[o][k]
    __shared__ float sA[128][68];   // row-major
    __shared__ float sb[64];
    int tid = threadIdx.x;
    for (int idx = tid; idx < 64*64; idx += 128) {
        int o = idx >> 6, k = idx & 63;
        sW[k][o] = W[idx];
    }
    if (tid < 64) sb[tid] = bias[tid];
    size_t row0 = (size_t)blockIdx.x * 128;
    const float4* Ab4 = (const float4*)(A + row0 * 64);
    for (int idx = tid; idx < 128*16; idx += 128) {
        int r = idx >> 4, c4 = idx & 15;
        ((float4*)sA[r])[c4] = Ab4[idx];
    }
    __syncthreads();
    int tr = tid >> 3;          // rows tr + 16*i
    int tc = (tid & 7) << 3;    // cols tc..tc+7
    float acc[8][8];
    #pragma unroll
    for (int i = 0; i < 8; i++)
        #pragma unroll
        for (int j = 0; j < 8; j++) acc[i][j] = sb[tc + j];
    #pragma unroll 4
    for (int k = 0; k < 64; k++) {
        float a[8];
        #pragma unroll
        for (int i = 0; i < 8; i++) a[i] = sA[tr + 16*i][k];
        float4 w0 = *(const float4*)&sW[k][tc];
        float4 w1 = *(const float4*)&sW[k][tc + 4];
        float w[8] = {w0.x, w0.y, w0.z, w0.w, w1.x, w1.y, w1.z, w1.w};
        #pragma unroll
        for (int i = 0; i < 8; i++)
            #pragma unroll
            for (int j = 0; j < 8; j++) acc[i][j] = fmaf(a[i], w[j], acc[i][j]);
    }
    #pragma unroll
    for (int i = 0; i < 8; i++) {
        float* o = out + (row0 + tr + 16*i) * 64 + tc;
        #pragma unroll
        for (int j = 0; j < 8; j++) o[j] = fmaxf(acc[i][j], 0.f);
    }
}

// ---------------- GEMM 2 + score: out = relu([aggr, x] @ U^T); score = out·p ----------------
__global__ void __launch_bounds__(128) k_gemm2_relu(
        const float* __restrict__ Agg, const float* __restrict__ X,
        const float* __restrict__ U, const float* __restrict__ p,
        float* __restrict__ out, float* __restrict__ score, int nrows)
{
    __shared__ float sU[128][68];   // sU[k][o] = U[o][k]; k<64 aggr-half, k>=64 x-half
    __shared__ float sA[128][68];
    __shared__ float sp[64];
    int tid = threadIdx.x;
    for (int idx = tid; idx < 64*128; idx += 128) {
        int o = idx >> 7, k = idx & 127;
        sU[k][o] = U[idx];
    }
    if (tid < 64) sp[tid] = p[tid];
    size_t row0 = (size_t)blockIdx.x * 128;
    int tr = tid >> 3;
    int tc = (tid & 7) << 3;
    float acc[8][8];
    #pragma unroll
    for (int i = 0; i < 8; i++)
        #pragma unroll
        for (int j = 0; j < 8; j++) acc[i][j] = 0.f;
    #pragma unroll
    for (int ph = 0; ph < 2; ph++) {
        const float4* Ab4 = (const float4*)((ph == 0 ? Agg : X) + row0 * 64);
        if (ph) __syncthreads();
        for (int idx = tid; idx < 128*16; idx += 128) {
            int r = idx >> 4, c4 = idx & 15;
            ((float4*)sA[r])[c4] = Ab4[idx];
        }
        __syncthreads();
        int kofs = ph << 6;
        #pragma unroll 4
        for (int k = 0; k < 64; k++) {
            float a[8];
            #pragma unroll
            for (int i = 0; i < 8; i++) a[i] = sA[tr + 16*i][k];
            float4 w0 = *(const float4*)&sU[kofs + k][tc];
            float4 w1 = *(const float4*)&sU[kofs + k][tc + 4];
            float w[8] = {w0.x, w0.y, w0.z, w0.w, w1.x, w1.y, w1.z, w1.w};
            #pragma unroll
            for (int i = 0; i < 8; i++)
                #pragma unroll
                for (int j = 0; j < 8; j++) acc[i][j] = fmaf(a[i], w[j], acc[i][j]);
        }
    }
    #pragma unroll
    for (int i = 0; i < 8; i++) {
        float* o = out + (row0 + tr + 16*i) * 64 + tc;
        float part = 0.f;
        #pragma unroll
        for (int j = 0; j < 8; j++) {
            float r = fmaxf(acc[i][j], 0.f);
            o[j] = r;
            part = fmaf(r, sp[tc + j], part);
        }
        part += __shfl_xor_sync(0xffffffffu, part, 1);
        part += __shfl_xor_sync(0xffffffffu, part, 2);
        part += __shfl_xor_sync(0xffffffffu, part, 4);
        if ((tid & 7) == 0) score[row0 + tr + 16*i] = part;
    }
}

// ---------------- fused CSR-build + gather-max aggregation (block per graph) ----------------
#define SMEM_CA ((3104 + EPG) * 4)
__global__ void __launch_bounds__(1024) k_csr_aggr(
        const int* __restrict__ ei, const int* __restrict__ invf,
        const float* __restrict__ msg, float* __restrict__ aggr, int n)
{
    extern __shared__ int smem[];
    int* slocal = smem;           // [1024] orig-local -> cur-local (-1 dead)
    int* scnt   = smem + 1024;    // [1024]
    int* scur   = smem + 2048;    // [1024] exclusive prefix -> running cursor
    int* swsum  = smem + 3072;    // [32]
    int* scsr   = smem + 3104;    // [EPG]
    int g = blockIdx.x, tid = threadIdx.x;
    int nb = g * N0V;
    {
        int t = invf[nb + tid];
        slocal[tid] = (t >= 0) ? (t - g*n) : -1;
        scnt[tid] = 0;
    }
    __syncthreads();
    int e0 = g * EPG;
    for (int e = tid; e < EPG; e += 1024) {
        int s = slocal[ei[e0 + e] - nb];
        int d = slocal[ei[ETOT + e0 + e] - nb];
        if ((s | d) >= 0) atomicAdd(&scnt[d], 1);
    }
    __syncthreads();
    {   // exclusive block scan of scnt into scur
        int lane = tid & 31, wid = tid >> 5;
        int v = scnt[tid];
        int x = v;
        #pragma unroll
        for (int o = 1; o < 32; o <<= 1) {
            int t = __shfl_up_sync(0xffffffffu, x, o);
            if (lane >= o) x += t;
        }
        if (lane == 31) swsum[wid] = x;
        __syncthreads();
        if (wid == 0) {
            int w = swsum[lane];
            int y = w;
            #pragma unroll
            for (int o = 1; o < 32; o <<= 1) {
                int t = __shfl_up_sync(0xffffffffu, y, o);
                if (lane >= o) y += t;
            }
            swsum[lane] = y - w;          // exclusive warp prefix
        }
        __syncthreads();
        scur[tid] = x - v + swsum[wid];   // exclusive prefix
    }
    __syncthreads();
    for (int e = tid; e < EPG; e += 1024) {
        int s = slocal[ei[e0 + e] - nb];
        int d = slocal[ei[ETOT + e0 + e] - nb];
        if ((s | d) >= 0) {
            int pos = atomicAdd(&scur[d], 1);
            scsr[pos] = s;
        }
    }
    __syncthreads();
    const float2* m2 = (const float2*)msg;
    int lane = tid & 31, w = tid >> 5;
    for (int i = w; i < n; i += 32) {
        int node = g*n + i;
        float2 acc = m2[(size_t)node*32 + lane];      // self-loop init
        int end = scur[i];
        int t = end - scnt[i];
        for (; t + 4 <= end; t += 4) {
            int s0 = scsr[t], s1 = scsr[t+1], s2 = scsr[t+2], s3 = scsr[t+3];
            float2 v0 = m2[(size_t)(g*n + s0)*32 + lane];
            float2 v1 = m2[(size_t)(g*n + s1)*32 + lane];
            float2 v2 = m2[(size_t)(g*n + s2)*32 + lane];
            float2 v3 = m2[(size_t)(g*n + s3)*32 + lane];
            v0.x = fmaxf(v0.x, v1.x); v0.y = fmaxf(v0.y, v1.y);
            v2.x = fmaxf(v2.x, v3.x); v2.y = fmaxf(v2.y, v3.y);
            v0.x = fmaxf(v0.x, v2.x); v0.y = fmaxf(v0.y, v2.y);
            acc.x = fmaxf(acc.x, v0.x); acc.y = fmaxf(acc.y, v0.y);
        }
        for (; t < end; t++) {
            float2 vv = m2[(size_t)(g*n + scsr[t])*32 + lane];
            acc.x = fmaxf(acc.x, vv.x); acc.y = fmaxf(acc.y, vv.y);
        }
        ((float2*)aggr)[(size_t)node*32 + lane] = acc;
    }
}

// ---------------- generic TopK + xnew + readout + inline invf-compose ----------------
__global__ void __launch_bounds__(1024) k_topk(
        const float* __restrict__ x, const float* __restrict__ score,
        const float* __restrict__ p, int n, int K,
        float* __restrict__ xnew, float* __restrict__ h, int* __restrict__ invf)
{
    __shared__ float sval[1024];
    __shared__ int   sidx[1024];
    __shared__ int   srank[1024];
    __shared__ float stan[672];    // K <= 656 here
    __shared__ float smx[16][64];
    __shared__ float ssm[16][64];
    __shared__ float sinv_s;
    int g = blockIdx.x, tid = threadIdx.x;
    if (tid == 0) {
        float s = 0.f;
        for (int k = 0; k < 64; k++) { float v = p[k]; s += v*v; }
        sinv_s = 1.f / sqrtf(s);
    }
    float v = (tid < n) ? score[(size_t)g*n + tid] : -INF_F;
    int   ix = tid;
    bitonic1024(v, ix, sval, sidx, tid);
    srank[sidx[tid]] = tid;
    if (tid < K) stan[tid] = tanhf(sval[tid] * sinv_s);
    __syncthreads();
    if (invf) {   // compose: original node -> new id (per-graph local)
        int nb = g * N0V;
        int t = invf[nb + tid];
        if (t >= 0) {
            int rk = srank[t - g*n];
            t = (rk < K) ? g*K + rk : -1;
        }
        invf[nb + tid] = t;
    }
    float mx = -INF_F, sm = 0.f;
    for (int idx = tid; idx < K*64; idx += 1024) {
        int j = idx >> 6, k = idx & 63;
        float val = x[((size_t)g*n + sidx[j])*64 + k] * stan[j];
        xnew[((size_t)g*K + j)*64 + k] = val;
        mx = fmaxf(mx, val); sm += val;
    }
    int part = tid >> 6, d = tid & 63;
    smx[part][d] = mx; ssm[part][d] = sm;
    __syncthreads();
    if (tid < 64) {
        float m = smx[0][tid], s = ssm[0][tid];
        #pragma unroll
        for (int t2 = 1; t2 < 16; t2++) { m = fmaxf(m, smx[t2][tid]); s += ssm[t2][tid]; }
        h[g*128 + tid]      += m;
        h[g*128 + 64 + tid] += s / (float)K;
    }
}

// ---------------- final MLP (block per graph) ----------------
__global__ void k_mlp(const float* __restrict__ h,
                      const float* __restrict__ l1W, const float* __restrict__ l1b,
                      const float* __restrict__ l2W, const float* __restrict__ l2b,
                      const float* __restrict__ l3W, const float* __restrict__ l3b,
                      float* __restrict__ out)
{
    int g = blockIdx.x, o = threadIdx.x;   // 64 threads
    __shared__ float sh[128], t1[64], t2[64];
    sh[o]      = h[g*128 + o];
    sh[64 + o] = h[g*128 + 64 + o];
    __syncthreads();
    float a = l1b[o];
    for (int k = 0; k < 128; k++) a = fmaf(sh[k], l1W[o*128 + k], a);
    t1[o] = fmaxf(a, 0.f);
    __syncthreads();
    float b = l2b[o];
    for (int k = 0; k < 64; k++) b = fmaf(t1[k], l2W[o*64 + k], b);
    t2[o] = fmaxf(b, 0.f);
    __syncthreads();
    float c = l3b[o];
    for (int k = 0; k < 64; k++) c = fmaf(t2[k], l3W[o*64 + k], c);
    out[g*64 + o] = 1.f / (1.f + expf(-c));
}

// ---------------- batch output: repeat(arange(B), K3) ----------------
__global__ void k_batch(float* __restrict__ out, int total)
{
    int i = blockIdx.x * blockDim.x + threadIdx.x;
    if (i < total) out[NB*DD + i] = (float)(i / KK3);
}

// ---------------- host ----------------
extern "C" void kernel_launch(void* const* d_in, const int* in_sizes, int n_in,
                              void* d_out, int out_size)
{
    const int*   x_ids = (const int*)d_in[0];
    const int*   ei    = (const int*)d_in[1];
    const float* emb   = (const float*)d_in[2];
    const float* W[3]  = {(const float*)d_in[3], (const float*)d_in[7],  (const float*)d_in[11]};
    const float* bb[3] = {(const float*)d_in[4], (const float*)d_in[8],  (const float*)d_in[12]};
    const float* U[3]  = {(const float*)d_in[5], (const float*)d_in[9],  (const float*)d_in[13]};
    const float* p[3]  = {(const float*)d_in[6], (const float*)d_in[10], (const float*)d_in[14]};
    const float* l1W = (const float*)d_in[15];
    const float* l1b = (const float*)d_in[16];
    const float* l2W = (const float*)d_in[17];
    const float* l2b = (const float*)d_in[18];
    const float* l3W = (const float*)d_in[19];
    const float* l3b = (const float*)d_in[20];

    float *xbase, *msg, *aggr, *h, *out2c, *scorec, *score;
    int *invf;
    cudaGetSymbolAddress((void**)&xbase,  g_xb);
    cudaGetSymbolAddress((void**)&msg,    g_msg);
    cudaGetSymbolAddress((void**)&aggr,   g_aggr);
    cudaGetSymbolAddress((void**)&score,  g_score);
    cudaGetSymbolAddress((void**)&invf,   g_invf);
    cudaGetSymbolAddress((void**)&h,      g_h);
    cudaGetSymbolAddress((void**)&out2c,  g_out2c);
    cudaGetSymbolAddress((void**)&scorec, g_scorec);

    static int smem_set = 0;
    if (!smem_set) {
        cudaFuncSetAttribute(k_csr_aggr, cudaFuncAttributeMaxDynamicSharedMemorySize, SMEM_CA);
        smem_set = 1;
    }

    float* xs0 = xbase;
    float* xs1 = xbase + (size_t)NTOT*DD;
    float* xs2 = xbase + (size_t)2*NTOT*DD;

    // ---- layer 1 via tables (4 distinct embeddings -> 64 combos) ----
    k_tab1<<<1, 128>>>(emb, W[0], bb[0], U[0], p[0], out2c, scorec);
    k_topk1<<<NB, 1024>>>(x_ids, ei, out2c, scorec, p[0], xs0, invf, h);

    // ---- layer 2 ----
    {
        int n = KK1, K = KK2, nrows = NB * KK1;
        k_gemm_relu<<<nrows/128, 128>>>(xs0, W[1], bb[1], msg, nrows);
        k_csr_aggr<<<NB, 1024, SMEM_CA>>>(ei, invf, msg, aggr, n);
        k_gemm2_relu<<<nrows/128, 128>>>(aggr, xs0, U[1], p[1], xs1, score, nrows);
        k_topk<<<NB, 1024>>>(xs1, score, p[1], n, K, xs2, h, invf);
    }

    // ---- layer 3 ----
    {
        int n = KK2, K = KK3, nrows = NB * KK2;
        k_gemm_relu<<<nrows/128, 128>>>(xs2, W[2], bb[2], msg, nrows);
        k_csr_aggr<<<NB, 1024, SMEM_CA>>>(ei, invf, msg, aggr, n);
        k_gemm2_relu<<<nrows/128, 128>>>(aggr, xs2, U[2], p[2], xs0, score, nrows);
        k_topk<<<NB, 1024>>>(xs0, score, p[2], n, K, xs1, h, (int*)0);
    }

    k_mlp<<<NB, 64>>>(h, l1W, l1b, l2W, l2b, l3W, l3b, (float*)d_out);

    if (out_size > NB*DD) {
        int total = out_size - NB*DD;
        k_batch<<<(total + 255)/256, 256>>>((float*)d_out, total);
    }
}

// round 14
// speedup vs baseline: 4.6951x; 1.1186x over previous
#include <cuda_runtime.h>
#include <math.h>

#define NB    128        // batch (graphs)
#define DD    64         // feature dim
#define N0V   1024       // nodes per graph, layer 0
#define NTOT  (NB*N0V)   // 131072
#define EPG   16384      // edges per graph (contiguous blocks)
#define ETOT  (NB*EPG)   // 2097152
#define KK1   820
#define KK2   656
#define KK3   525

#define INF_F __int_as_float(0x7f800000)

// ---------------- scratch (device globals; no allocations) ----------------
__device__ float g_xb[3][NTOT*DD];     // ping-pong x buffers
__device__ float g_msg[NTOT*DD];
__device__ float g_aggr[NTOT*DD];
__device__ float g_score[NTOT];        // per-row score (from gemm2 epilogue)
__device__ int   g_invf[NTOT];         // composed: original node -> current id (-1 dropped)
__device__ float g_h[NB*2*DD];
__device__ float g_out2c[64*64];       // layer-1 update table per combo
__device__ float g_scorec[64];         // layer-1 score per combo

// ---------------- hybrid bitonic sort: 1024 elems, regs + shfl for j<32 ----------------
// Descending by value, ascending index on ties (matches jax.lax.top_k).
__device__ __forceinline__ void bitonic1024(float& v, int& i, float* sval, int* sidx, int tid)
{
    for (int ksz = 2; ksz <= 1024; ksz <<= 1) {
        for (int j = ksz >> 1; j > 0; j >>= 1) {
            bool descHere = ((tid & ksz) == 0);
            bool lower    = ((tid & j) == 0);
            float vp; int ip;
            if (j >= 32) {
                sval[tid] = v; sidx[tid] = i;
                __syncthreads();
                vp = sval[tid ^ j]; ip = sidx[tid ^ j];
                __syncthreads();
            } else {
                vp = __shfl_xor_sync(0xffffffffu, v, j);
                ip = __shfl_xor_sync(0xffffffffu, i, j);
            }
            float vlo = lower ? v : vp;  int ilo = lower ? i : ip;
            float vhi = lower ? vp : v;  int ihi = lower ? ip : i;
            bool a_first = (vlo > vhi) || (vlo == vhi && ilo < ihi);
            if (descHere != a_first) { v = vp; i = ip; }
        }
    }
    sval[tid] = v; sidx[tid] = i;
    __syncthreads();
}

// ---------------- layer-1 tables: 64 combos (id, neighbor-id mask) ----------------
__global__ void k_tab1(const float* __restrict__ emb, const float* __restrict__ W1,
                       const float* __restrict__ b1, const float* __restrict__ U1,
                       const float* __restrict__ p1,
                       float* __restrict__ out2c, float* __restrict__ scorec)
{
    __shared__ float smsg[4][64];
    __shared__ float saggr[64][65];
    __shared__ float sout[64][65];
    __shared__ float sp[64];
    int t = threadIdx.x;               // 128 threads
    if (t < 64) {
        sp[t] = p1[t];
        float b = b1[t];
        for (int id = 0; id < 4; id++) {
            float acc = b;
            for (int k = 0; k < 64; k++) acc = fmaf(emb[id*64 + k], W1[t*64 + k], acc);
            smsg[id][t] = fmaxf(acc, 0.f);
        }
    }
    __syncthreads();
    {
        int c = t >> 1, h = t & 1;
        int id = c >> 4;
        int m = (c & 15) | (1 << id);
        for (int k = h*32; k < h*32 + 32; k++) {
            float v = -INF_F;
            #pragma unroll
            for (int b = 0; b < 4; b++)
                if ((m >> b) & 1) v = fmaxf(v, smsg[b][k]);
            saggr[c][k] = v;
        }
    }
    __syncthreads();
    {
        int c = t >> 1, h = t & 1;
        int id = c >> 4;
        for (int o = h*32; o < h*32 + 32; o++) {
            float acc = 0.f;
            for (int k = 0; k < 64; k++) acc = fmaf(saggr[c][k], U1[o*128 + k], acc);
            for (int k = 0; k < 64; k++) acc = fmaf(emb[id*64 + k], U1[o*128 + 64 + k], acc);
            float r = fmaxf(acc, 0.f);
            sout[c][o] = r;
            out2c[c*64 + o] = r;
        }
    }
    __syncthreads();
    if (t < 64) {
        float s = 0.f;
        for (int o = 0; o < 64; o++) s += sout[t][o] * sp[o];
        scorec[t] = s;
    }
}

// ---------------- layer-1: mask build + topk + xnew + readout (h ASSIGNED here) ----------------
__global__ void __launch_bounds__(1024) k_topk1(
        const int* __restrict__ ids, const int* __restrict__ ei,
        const float* __restrict__ out2c, const float* __restrict__ scorec,
        const float* __restrict__ p,
        float* __restrict__ xnew, int* __restrict__ invf, float* __restrict__ h)
{
    __shared__ int   sids[1024];
    __shared__ int   smask[1024];
    __shared__ float sval[1024];
    __shared__ int   sidx[1024];
    __shared__ float stan[KK1];
    __shared__ float stab[64];
    __shared__ float sout[64*64];
    __shared__ float smx[16][64];
    __shared__ float ssm[16][64];
    __shared__ float sinv_s;
    int g = blockIdx.x, tid = threadIdx.x;
    int nb = g * 1024;
    sids[tid]  = ids[nb + tid];
    smask[tid] = 0;
    if (tid < 64) stab[tid] = scorec[tid];
    for (int i = tid; i < 64*64; i += 1024) sout[i] = out2c[i];
    if (tid == 0) {
        float s = 0.f;
        for (int k = 0; k < 64; k++) { float v = p[k]; s += v*v; }
        sinv_s = 1.f / sqrtf(s);
    }
    __syncthreads();
    int e0 = g * EPG;
    for (int e = tid; e < EPG; e += 1024) {
        int s = ei[e0 + e] - nb;
        int d = ei[ETOT + e0 + e] - nb;
        atomicOr(&smask[d], 1 << sids[s]);
    }
    invf[nb + tid] = -1;
    __syncthreads();
    float v = stab[(sids[tid] << 4) | smask[tid]];
    int   ix = tid;
    bitonic1024(v, ix, sval, sidx, tid);
    if (tid < KK1) {
        invf[nb + sidx[tid]] = g*KK1 + tid;
        stan[tid] = tanhf(sval[tid] * sinv_s);
    }
    __syncthreads();
    float mx = -INF_F, sm = 0.f;
    for (int idx = tid; idx < KK1*64; idx += 1024) {
        int j = idx >> 6, k = idx & 63;
        int node = sidx[j];
        int c = (sids[node] << 4) | smask[node];
        float val = sout[c*64 + k] * stan[j];
        xnew[((size_t)g*KK1 + j)*64 + k] = val;
        mx = fmaxf(mx, val); sm += val;
    }
    int part = tid >> 6, d = tid & 63;
    smx[part][d] = mx; ssm[part][d] = sm;
    __syncthreads();
    if (tid < 64) {
        float m = smx[0][tid], s = ssm[0][tid];
        #pragma unroll
        for (int t2 = 1; t2 < 16; t2++) { m = fmaxf(m, smx[t2][tid]); s += ssm[t2][tid]; }
        h[g*128 + tid]      = m;                 // first layer: assign (no zero-kernel)
        h[g*128 + 64 + tid] = s / (float)KK1;
    }
}

// ---------------- GEMM 1: msg = relu(x @ W^T + b), K = 64 ----------------
// 256 threads, 128 rows/block, 8x4 per-thread tile; ~60 regs -> 4 blocks/SM (32 warps).
__global__ void __launch_bounds__(256, 4) k_gemm_relu(
        const float* __restrict__ A, const float* __restrict__ W,
        const float* __restrict__ bias, float* __restrict__ out, int nrows)
{
    __shared__ float sW[64][68];    // sW[k][o] = W[o][k]
    __shared__ float sA[128][68];   // row-major (stride 68 keeps float4 alignment)
    __shared__ float sb[64];
    int tid = threadIdx.x;
    for (int idx = tid; idx < 64*64; idx += 256) {
        int o = idx >> 6, k = idx & 63;
        sW[k][o] = W[idx];
    }
    if (tid < 64) sb[tid] = bias[tid];
    size_t row0 = (size_t)blockIdx.x * 128;
    const float4* Ab4 = (const float4*)(A + row0 * 64);
    for (int idx = tid; idx < 128*16; idx += 256) {
        int r = idx >> 4, c4 = idx & 15;
        ((float4*)sA[r])[c4] = Ab4[idx];
    }
    __syncthreads();
    int tr = tid >> 4;          // 0..15 : rows tr + 16*i
    int tc = (tid & 15) << 2;   // 0..60 : cols tc..tc+3
    float acc[8][4];
    #pragma unroll
    for (int i = 0; i < 8; i++) {
        #pragma unroll
        for (int j = 0; j < 4; j++) acc[i][j] = sb[tc + j];
    }
    #pragma unroll 4
    for (int k = 0; k < 64; k++) {
        float a[8];
        #pragma unroll
        for (int i = 0; i < 8; i++) a[i] = sA[tr + 16*i][k];
        float4 w4 = *(const float4*)&sW[k][tc];
        float w[4] = {w4.x, w4.y, w4.z, w4.w};
        #pragma unroll
        for (int i = 0; i < 8; i++)
            #pragma unroll
            for (int j = 0; j < 4; j++) acc[i][j] = fmaf(a[i], w[j], acc[i][j]);
    }
    #pragma unroll
    for (int i = 0; i < 8; i++) {
        float4 r4;
        r4.x = fmaxf(acc[i][0], 0.f);
        r4.y = fmaxf(acc[i][1], 0.f);
        r4.z = fmaxf(acc[i][2], 0.f);
        r4.w = fmaxf(acc[i][3], 0.f);
        *(float4*)(out + (row0 + tr + 16*i) * 64 + tc) = r4;
    }
}

// ---------------- GEMM 2 + score: out = relu([aggr, x] @ U^T); score = out·p ----------------
// 256 threads, 128 rows/block, 8x4 tile; two K=64 phases sharing one A buffer.
__global__ void __launch_bounds__(256, 3) k_gemm2_relu(
        const float* __restrict__ Agg, const float* __restrict__ X,
        const float* __restrict__ U, const float* __restrict__ p,
        float* __restrict__ out, float* __restrict__ score, int nrows)
{
    __shared__ float sU[128][68];   // sU[k][o] = U[o][k]; k<64 aggr-half, k>=64 x-half
    __shared__ float sA[128][68];
    __shared__ float sp[64];
    int tid = threadIdx.x;
    for (int idx = tid; idx < 64*128; idx += 256) {
        int o = idx >> 7, k = idx & 127;
        sU[k][o] = U[idx];
    }
    if (tid < 64) sp[tid] = p[tid];
    size_t row0 = (size_t)blockIdx.x * 128;
    int tr = tid >> 4;
    int tc = (tid & 15) << 2;
    float acc[8][4];
    #pragma unroll
    for (int i = 0; i < 8; i++) {
        #pragma unroll
        for (int j = 0; j < 4; j++) acc[i][j] = 0.f;
    }
    #pragma unroll
    for (int ph = 0; ph < 2; ph++) {
        const float4* Ab4 = (const float4*)((ph == 0 ? Agg : X) + row0 * 64);
        if (ph) __syncthreads();
        for (int idx = tid; idx < 128*16; idx += 256) {
            int r = idx >> 4, c4 = idx & 15;
            ((float4*)sA[r])[c4] = Ab4[idx];
        }
        __syncthreads();
        int kofs = ph << 6;
        #pragma unroll 4
        for (int k = 0; k < 64; k++) {
            float a[8];
            #pragma unroll
            for (int i = 0; i < 8; i++) a[i] = sA[tr + 16*i][k];
            float4 w4 = *(const float4*)&sU[kofs + k][tc];
            float w[4] = {w4.x, w4.y, w4.z, w4.w};
            #pragma unroll
            for (int i = 0; i < 8; i++)
                #pragma unroll
                for (int j = 0; j < 4; j++) acc[i][j] = fmaf(a[i], w[j], acc[i][j]);
        }
    }
    #pragma unroll
    for (int i = 0; i < 8; i++) {
        float4 r4;
        r4.x = fmaxf(acc[i][0], 0.f);
        r4.y = fmaxf(acc[i][1], 0.f);
        r4.z = fmaxf(acc[i][2], 0.f);
        r4.w = fmaxf(acc[i][3], 0.f);
        *(float4*)(out + (row0 + tr + 16*i) * 64 + tc) = r4;
        float part = fmaf(r4.x, sp[tc], fmaf(r4.y, sp[tc+1],
                     fmaf(r4.z, sp[tc+2], r4.w * sp[tc+3])));
        // reduce across the 16 lanes sharing this row (xor<16 stays in group)
        part += __shfl_xor_sync(0xffffffffu, part, 1);
        part += __shfl_xor_sync(0xffffffffu, part, 2);
        part += __shfl_xor_sync(0xffffffffu, part, 4);
        part += __shfl_xor_sync(0xffffffffu, part, 8);
        if ((tid & 15) == 0) score[row0 + tr + 16*i] = part;
    }
}

// ---------------- fused CSR-build + gather-max aggregation ----------------
// TWO blocks per graph (dst halves) -> 256 blocks, all SMs busy, gather tail halved.
#define SMEM_CA ((2080 + EPG) * 4)
__global__ void __launch_bounds__(1024) k_csr_aggr(
        const int* __restrict__ ei, const int* __restrict__ invf,
        const float* __restrict__ msg, float* __restrict__ aggr, int n, int nh)
{
    extern __shared__ int smem[];
    int* slocal = smem;           // [1024] orig-local -> cur-local (-1 dead)
    int* scnt   = smem + 1024;    // [512]
    int* scur   = smem + 1536;    // [512]
    int* swsum  = smem + 2048;    // [32]
    int* scsr   = smem + 2080;    // [EPG]
    int g = blockIdx.x >> 1, half = blockIdx.x & 1;
    int tid = threadIdx.x;
    int d0 = half * nh;
    int dcnt = min(n - d0, nh);   // dsts handled by this block
    int nb = g * N0V;
    {
        int t = invf[nb + tid];
        slocal[tid] = (t >= 0) ? (t - g*n) : -1;
    }
    if (tid < nh) scnt[tid] = 0;
    __syncthreads();
    int e0 = g * EPG;
    for (int e = tid; e < EPG; e += 1024) {
        int s = slocal[ei[e0 + e] - nb];
        int d = slocal[ei[ETOT + e0 + e] - nb];
        if ((s | d) >= 0) {
            int dl = d - d0;
            if ((unsigned)dl < (unsigned)dcnt) atomicAdd(&scnt[dl], 1);
        }
    }
    __syncthreads();
    int lane = tid & 31, wid = tid >> 5;
    {   // exclusive scan of scnt[0..511] into scur (warps 0..15)
        int v = 0, x = 0;
        if (tid < 512) {
            v = scnt[tid];
            x = v;
            #pragma unroll
            for (int o = 1; o < 32; o <<= 1) {
                int t = __shfl_up_sync(0xffffffffu, x, o);
                if (lane >= o) x += t;
            }
            if (lane == 31) swsum[wid] = x;
        }
        __syncthreads();
        if (wid == 0) {
            int w16 = (lane < 16) ? swsum[lane] : 0;
            int y = w16;
            #pragma unroll
            for (int o = 1; o < 16; o <<= 1) {
                int t = __shfl_up_sync(0xffffffffu, y, o);
                if (lane >= o) y += t;
            }
            if (lane < 16) swsum[lane] = y - w16;
        }
        __syncthreads();
        if (tid < 512) scur[tid] = x - v + swsum[wid];
        __syncthreads();
    }
    for (int e = tid; e < EPG; e += 1024) {
        int s = slocal[ei[e0 + e] - nb];
        int d = slocal[ei[ETOT + e0 + e] - nb];
        if ((s | d) >= 0) {
            int dl = d - d0;
            if ((unsigned)dl < (unsigned)dcnt) {
                int pos = atomicAdd(&scur[dl], 1);
                scsr[pos] = s;
            }
        }
    }
    __syncthreads();
    const float2* m2 = (const float2*)msg;
    for (int i = wid; i < dcnt; i += 32) {
        int node = g*n + d0 + i;
        float2 acc = m2[(size_t)node*32 + lane];      // self-loop init
        int end = scur[i];
        int t = end - scnt[i];
        for (; t + 4 <= end; t += 4) {
            int s0 = scsr[t], s1 = scsr[t+1], s2 = scsr[t+2], s3 = scsr[t+3];
            float2 v0 = m2[(size_t)(g*n + s0)*32 + lane];
            float2 v1 = m2[(size_t)(g*n + s1)*32 + lane];
            float2 v2 = m2[(size_t)(g*n + s2)*32 + lane];
            float2 v3 = m2[(size_t)(g*n + s3)*32 + lane];
            v0.x = fmaxf(v0.x, v1.x); v0.y = fmaxf(v0.y, v1.y);
            v2.x = fmaxf(v2.x, v3.x); v2.y = fmaxf(v2.y, v3.y);
            v0.x = fmaxf(v0.x, v2.x); v0.y = fmaxf(v0.y, v2.y);
            acc.x = fmaxf(acc.x, v0.x); acc.y = fmaxf(acc.y, v0.y);
        }
        for (; t < end; t++) {
            float2 vv = m2[(size_t)(g*n + scsr[t])*32 + lane];
            acc.x = fmaxf(acc.x, vv.x); acc.y = fmaxf(acc.y, vv.y);
        }
        ((float2*)aggr)[(size_t)node*32 + lane] = acc;
    }
}

// ---------------- generic TopK + xnew + readout + inline invf-compose ----------------
__global__ void __launch_bounds__(1024) k_topk(
        const float* __restrict__ x, const float* __restrict__ score,
        const float* __restrict__ p, int n, int K,
        float* __restrict__ xnew, float* __restrict__ h, int* __restrict__ invf)
{
    __shared__ float sval[1024];
    __shared__ int   sidx[1024];
    __shared__ int   srank[1024];
    __shared__ float stan[672];    // K <= 656 here
    __shared__ float smx[16][64];
    __shared__ float ssm[16][64];
    __shared__ float sinv_s;
    int g = blockIdx.x, tid = threadIdx.x;
    if (tid == 0) {
        float s = 0.f;
        for (int k = 0; k < 64; k++) { float v = p[k]; s += v*v; }
        sinv_s = 1.f / sqrtf(s);
    }
    float v = (tid < n) ? score[(size_t)g*n + tid] : -INF_F;
    int   ix = tid;
    bitonic1024(v, ix, sval, sidx, tid);
    srank[sidx[tid]] = tid;
    if (tid < K) stan[tid] = tanhf(sval[tid] * sinv_s);
    __syncthreads();
    if (invf) {   // compose: original node -> new id (per-graph local)
        int nb = g * N0V;
        int t = invf[nb + tid];
        if (t >= 0) {
            int rk = srank[t - g*n];
            t = (rk < K) ? g*K + rk : -1;
        }
        invf[nb + tid] = t;
    }
    float mx = -INF_F, sm = 0.f;
    for (int idx = tid; idx < K*64; idx += 1024) {
        int j = idx >> 6, k = idx & 63;
        float val = x[((size_t)g*n + sidx[j])*64 + k] * stan[j];
        xnew[((size_t)g*K + j)*64 + k] = val;
        mx = fmaxf(mx, val); sm += val;
    }
    int part = tid >> 6, d = tid & 63;
    smx[part][d] = mx; ssm[part][d] = sm;
    __syncthreads();
    if (tid < 64) {
        float m = smx[0][tid], s = ssm[0][tid];
        #pragma unroll
        for (int t2 = 1; t2 < 16; t2++) { m = fmaxf(m, smx[t2][tid]); s += ssm[t2][tid]; }
        h[g*128 + tid]      += m;
        h[g*128 + 64 + tid] += s / (float)K;
    }
}

// ---------------- final MLP (block per graph) ----------------
__global__ void k_mlp(const float* __restrict__ h,
                      const float* __restrict__ l1W, const float* __restrict__ l1b,
                      const float* __restrict__ l2W, const float* __restrict__ l2b,
                      const float* __restrict__ l3W, const float* __restrict__ l3b,
                      float* __restrict__ out)
{
    int g = blockIdx.x, o = threadIdx.x;   // 64 threads
    __shared__ float sh[128], t1[64], t2[64];
    sh[o]      = h[g*128 + o];
    sh[64 + o] = h[g*128 + 64 + o];
    __syncthreads();
    float a = l1b[o];
    for (int k = 0; k < 128; k++) a = fmaf(sh[k], l1W[o*128 + k], a);
    t1[o] = fmaxf(a, 0.f);
    __syncthreads();
    float b = l2b[o];
    for (int k = 0; k < 64; k++) b = fmaf(t1[k], l2W[o*64 + k], b);
    t2[o] = fmaxf(b, 0.f);
    __syncthreads();
    float c = l3b[o];
    for (int k = 0; k < 64; k++) c = fmaf(t2[k], l3W[o*64 + k], c);
    out[g*64 + o] = 1.f / (1.f + expf(-c));
}

// ---------------- batch output: repeat(arange(B), K3) ----------------
__global__ void k_batch(float* __restrict__ out, int total)
{
    int i = blockIdx.x * blockDim.x + threadIdx.x;
    if (i < total) out[NB*DD + i] = (float)(i / KK3);
}

// ---------------- host ----------------
extern "C" void kernel_launch(void* const* d_in, const int* in_sizes, int n_in,
                              void* d_out, int out_size)
{
    const int*   x_ids = (const int*)d_in[0];
    const int*   ei    = (const int*)d_in[1];
    const float* emb   = (const float*)d_in[2];
    const float* W[3]  = {(const float*)d_in[3], (const float*)d_in[7],  (const float*)d_in[11]};
    const float* bb[3] = {(const float*)d_in[4], (const float*)d_in[8],  (const float*)d_in[12]};
    const float* U[3]  = {(const float*)d_in[5], (const float*)d_in[9],  (const float*)d_in[13]};
    const float* p[3]  = {(const float*)d_in[6], (const float*)d_in[10], (const float*)d_in[14]};
    const float* l1W = (const float*)d_in[15];
    const float* l1b = (const float*)d_in[16];
    const float* l2W = (const float*)d_in[17];
    const float* l2b = (const float*)d_in[18];
    const float* l3W = (const float*)d_in[19];
    const float* l3b = (const float*)d_in[20];

    float *xbase, *msg, *aggr, *h, *out2c, *scorec, *score;
    int *invf;
    cudaGetSymbolAddress((void**)&xbase,  g_xb);
    cudaGetSymbolAddress((void**)&msg,    g_msg);
    cudaGetSymbolAddress((void**)&aggr,   g_aggr);
    cudaGetSymbolAddress((void**)&score,  g_score);
    cudaGetSymbolAddress((void**)&invf,   g_invf);
    cudaGetSymbolAddress((void**)&h,      g_h);
    cudaGetSymbolAddress((void**)&out2c,  g_out2c);
    cudaGetSymbolAddress((void**)&scorec, g_scorec);

    static int smem_set = 0;
    if (!smem_set) {
        cudaFuncSetAttribute(k_csr_aggr, cudaFuncAttributeMaxDynamicSharedMemorySize, SMEM_CA);
        smem_set = 1;
    }

    float* xs0 = xbase;
    float* xs1 = xbase + (size_t)NTOT*DD;
    float* xs2 = xbase + (size_t)2*NTOT*DD;

    // ---- layer 1 via tables (4 distinct embeddings -> 64 combos) ----
    k_tab1<<<1, 128>>>(emb, W[0], bb[0], U[0], p[0], out2c, scorec);
    k_topk1<<<NB, 1024>>>(x_ids, ei, out2c, scorec, p[0], xs0, invf, h);

    // ---- layer 2 ----
    {
        int n = KK1, K = KK2, nrows = NB * KK1;
        int nh = (n + 1) / 2;
        k_gemm_relu<<<nrows/128, 256>>>(xs0, W[1], bb[1], msg, nrows);
        k_csr_aggr<<<2*NB, 1024, SMEM_CA>>>(ei, invf, msg, aggr, n, nh);
        k_gemm2_relu<<<nrows/128, 256>>>(aggr, xs0, U[1], p[1], xs1, score, nrows);
        k_topk<<<NB, 1024>>>(xs1, score, p[1], n, K, xs2, h, invf);
    }

    // ---- layer 3 ----
    {
        int n = KK2, K = KK3, nrows = NB * KK2;
        int nh = (n + 1) / 2;
        k_gemm_relu<<<nrows/128, 256>>>(xs2, W[2], bb[2], msg, nrows);
        k_csr_aggr<<<2*NB, 1024, SMEM_CA>>>(ei, invf, msg, aggr, n, nh);
        k_gemm2_relu<<<nrows/128, 256>>>(aggr, xs2, U[2], p[2], xs0, score, nrows);
        k_topk<<<NB, 1024>>>(xs0, score, p[2], n, K, xs1, h, (int*)0);
    }

    k_mlp<<<NB, 64>>>(h, l1W, l1b, l2W, l2b, l3W, l3b, (float*)d_out);

    if (out_size > NB*DD) {
        int total = out_size - NB*DD;
        k_batch<<<(total + 255)/256, 256>>>((float*)d_out, total);
    }
}